// round 1
// baseline (speedup 1.0000x reference)
#include <cuda_runtime.h>

#define DM    1024
#define HH    16
#define DK    64
#define BB    2
#define LL    2048
#define NROWS (BB*LL)        /* 4096 */
#define DFF   4096
#define EPSLN 1e-5f

// ---------------- scratch (device globals; no allocations allowed) ----------
__device__ float g_Q[(size_t)BB*HH*LL*DK];
__device__ float g_K[(size_t)BB*HH*LL*DK];
__device__ float g_V[(size_t)BB*HH*LL*DK];
__device__ float g_O[(size_t)NROWS*DM];    // attention output, [B*L, H*DV]
__device__ float g_y1[(size_t)NROWS*DM];   // x + mha
__device__ float g_h1[(size_t)NROWS*DM];   // LN1 output
__device__ float g_ff[(size_t)NROWS*DFF];  // relu(h1 W1 + b1)
__device__ float g_y2[(size_t)NROWS*DM];   // h1 + ff W2

// ---------------- QKV projection: per-head GEMM [4096,1024]x[1024,64] -------
__global__ __launch_bounds__(256) void qkv_kernel(
    const float* __restrict__ x,
    const float* __restrict__ Wq, const float* __restrict__ bq,
    const float* __restrict__ Wk, const float* __restrict__ bk,
    const float* __restrict__ Wv, const float* __restrict__ bv)
{
    __shared__ float Ast[16][128];
    __shared__ float Bs [16][64];
    const int tid = threadIdx.x;
    const int tx = tid & 15, ty = tid >> 4;
    const int h = blockIdx.y;
    const int z = blockIdx.z;
    const float* W    = (z == 0) ? Wq : (z == 1) ? Wk : Wv;
    const float* bias = (z == 0) ? bq : (z == 1) ? bk : bv;
    float* outp       = (z == 0) ? g_Q : (z == 1) ? g_K : g_V;
    W += (size_t)h * DM * DK;
    const int m0 = blockIdx.x * 128;

    float acc[8][4] = {};
    const int ar  = tid >> 2;          // 0..63
    const int akq = (tid & 3) * 4;     // 0,4,8,12
    const int br  = tid >> 4;          // 0..15
    const int bc  = (tid & 15) * 4;    // 0..60

    for (int k0 = 0; k0 < DM; k0 += 16) {
        #pragma unroll
        for (int rr = 0; rr < 2; rr++) {
            int r = ar + rr * 64;
            float4 v = *(const float4*)&x[(size_t)(m0 + r) * DM + k0 + akq];
            Ast[akq + 0][r] = v.x; Ast[akq + 1][r] = v.y;
            Ast[akq + 2][r] = v.z; Ast[akq + 3][r] = v.w;
        }
        *(float4*)&Bs[br][bc] = *(const float4*)&W[(size_t)(k0 + br) * DK + bc];
        __syncthreads();
        #pragma unroll
        for (int kk = 0; kk < 16; kk++) {
            float4 a0 = *(const float4*)&Ast[kk][ty * 8];
            float4 a1 = *(const float4*)&Ast[kk][ty * 8 + 4];
            float4 bv4 = *(const float4*)&Bs[kk][tx * 4];
            float a[8] = {a0.x, a0.y, a0.z, a0.w, a1.x, a1.y, a1.z, a1.w};
            float bb[4] = {bv4.x, bv4.y, bv4.z, bv4.w};
            #pragma unroll
            for (int i = 0; i < 8; i++)
                #pragma unroll
                for (int j = 0; j < 4; j++)
                    acc[i][j] += a[i] * bb[j];
        }
        __syncthreads();
    }
    #pragma unroll
    for (int i = 0; i < 8; i++) {
        int n = m0 + ty * 8 + i;
        int b = n >> 11, l = n & 2047;
        size_t base = ((size_t)(b * HH + h) * LL + l) * DK;
        #pragma unroll
        for (int j = 0; j < 4; j++) {
            int c = tx * 4 + j;
            outp[base + c] = acc[i][j] + bias[h * DK + c];
        }
    }
}

// ---------------- fused flash attention ------------------------------------
#define BQ  128
#define BKT 128
#define QST 132   /* row stride of transposed Q/K tiles (64 x 132) */
#define VST 68    /* row stride of V tile (128 x 68) */
#define PST 132   /* row stride of P tile (128 x 132) */
#define RST 17

#define ATT_SMEM_FLOATS (64*QST + 64*QST + 128*VST + 128*PST + 128*RST + 128 + 128)

__global__ __launch_bounds__(256) void attn_kernel(float* __restrict__ Oc,
                                                   const float* __restrict__ Q,
                                                   const float* __restrict__ K,
                                                   const float* __restrict__ V)
{
    extern __shared__ float sm[];
    float* Qst = sm;                   // [64][QST]  (transposed, pre-scaled)
    float* Kst = Qst + 64 * QST;       // [64][QST]  (transposed)
    float* Vs  = Kst + 64 * QST;       // [128][VST]
    float* Ps  = Vs  + 128 * VST;      // [128][PST]
    float* red = Ps  + 128 * PST;      // [128][RST]
    float* m_s = red + 128 * RST;      // [128]
    float* l_s = m_s + 128;            // [128]

    const int tid = threadIdx.x;
    const int tx = tid & 15, ty = tid >> 4;
    const int bh = blockIdx.y, qt = blockIdx.x;
    const float* Qp = Q + (size_t)bh * LL * DK + (size_t)qt * BQ * DK;
    const float* Kb = K + (size_t)bh * LL * DK;
    const float* Vb = V + (size_t)bh * LL * DK;

    for (int idx = tid; idx < BQ * DK; idx += 256) {
        int r = idx >> 6, c = idx & 63;
        Qst[c * QST + r] = Qp[idx] * 0.125f;   // 1/sqrt(64)
    }
    if (tid < 128) { m_s[tid] = -1e30f; l_s[tid] = 0.f; }
    float acc[8][4] = {};
    __syncthreads();

    for (int kt = 0; kt < LL / BKT; kt++) {
        const float* Kp = Kb + (size_t)kt * BKT * DK;
        const float* Vp = Vb + (size_t)kt * BKT * DK;
        for (int idx = tid; idx < BKT * DK; idx += 256) {
            int r = idx >> 6, c = idx & 63;
            Kst[c * QST + r] = Kp[idx];
            Vs[r * VST + c]  = Vp[idx];
        }
        __syncthreads();

        // S = Qs @ Ks^T  (per-thread 8x8)
        float s[8][8] = {};
        #pragma unroll 8
        for (int kk = 0; kk < DK; kk++) {
            float4 qa = *(const float4*)&Qst[kk * QST + ty * 8];
            float4 qb = *(const float4*)&Qst[kk * QST + ty * 8 + 4];
            float4 ka = *(const float4*)&Kst[kk * QST + tx * 8];
            float4 kb = *(const float4*)&Kst[kk * QST + tx * 8 + 4];
            float a[8] = {qa.x, qa.y, qa.z, qa.w, qb.x, qb.y, qb.z, qb.w};
            float b[8] = {ka.x, ka.y, ka.z, ka.w, kb.x, kb.y, kb.z, kb.w};
            #pragma unroll
            for (int i = 0; i < 8; i++)
                #pragma unroll
                for (int j = 0; j < 8; j++)
                    s[i][j] += a[i] * b[j];
        }

        float m_old[8], m_new[8], alpha[8], rs[8];
        #pragma unroll
        for (int i = 0; i < 8; i++) {
            int row = ty * 8 + i;
            float rm = s[i][0];
            #pragma unroll
            for (int j = 1; j < 8; j++) rm = fmaxf(rm, s[i][j]);
            red[row * RST + tx] = rm;
            m_old[i] = m_s[row];
        }
        __syncthreads();
        #pragma unroll
        for (int i = 0; i < 8; i++) {
            int row = ty * 8 + i;
            float tm = red[row * RST];
            #pragma unroll
            for (int t = 1; t < 16; t++) tm = fmaxf(tm, red[row * RST + t]);
            m_new[i] = fmaxf(m_old[i], tm);
            alpha[i] = __expf(m_old[i] - m_new[i]);
            float sum = 0.f;
            #pragma unroll
            for (int j = 0; j < 8; j++) {
                s[i][j] = __expf(s[i][j] - m_new[i]);
                sum += s[i][j];
            }
            rs[i] = sum;
        }
        __syncthreads();
        #pragma unroll
        for (int i = 0; i < 8; i++) red[(ty * 8 + i) * RST + tx] = rs[i];
        __syncthreads();
        #pragma unroll
        for (int i = 0; i < 8; i++) {
            int row = ty * 8 + i;
            if (tx == 0) {
                float ts = 0.f;
                #pragma unroll
                for (int t = 0; t < 16; t++) ts += red[row * RST + t];
                l_s[row] = l_s[row] * alpha[i] + ts;
                m_s[row] = m_new[i];
            }
            #pragma unroll
            for (int j = 0; j < 4; j++) acc[i][j] *= alpha[i];
            float4 p0 = make_float4(s[i][0], s[i][1], s[i][2], s[i][3]);
            float4 p1 = make_float4(s[i][4], s[i][5], s[i][6], s[i][7]);
            *(float4*)&Ps[row * PST + tx * 8]     = p0;
            *(float4*)&Ps[row * PST + tx * 8 + 4] = p1;
        }
        __syncthreads();

        // acc += P @ V  (per-thread 8 rows x 4 cols)
        for (int k4 = 0; k4 < BKT; k4 += 4) {
            float4 v0 = *(const float4*)&Vs[(k4 + 0) * VST + tx * 4];
            float4 v1 = *(const float4*)&Vs[(k4 + 1) * VST + tx * 4];
            float4 v2 = *(const float4*)&Vs[(k4 + 2) * VST + tx * 4];
            float4 v3 = *(const float4*)&Vs[(k4 + 3) * VST + tx * 4];
            #pragma unroll
            for (int i = 0; i < 8; i++) {
                float4 p = *(const float4*)&Ps[(ty * 8 + i) * PST + k4];
                acc[i][0] += p.x * v0.x + p.y * v1.x + p.z * v2.x + p.w * v3.x;
                acc[i][1] += p.x * v0.y + p.y * v1.y + p.z * v2.y + p.w * v3.y;
                acc[i][2] += p.x * v0.z + p.y * v1.z + p.z * v2.z + p.w * v3.z;
                acc[i][3] += p.x * v0.w + p.y * v1.w + p.z * v2.w + p.w * v3.w;
            }
        }
        __syncthreads();
    }

    const int b = bh >> 4, h = bh & 15;
    #pragma unroll
    for (int i = 0; i < 8; i++) {
        int row = ty * 8 + i;
        float inv = 1.f / l_s[row];
        size_t n = (size_t)b * LL + (size_t)qt * BQ + row;
        float* op = Oc + n * DM + h * DK + tx * 4;
        #pragma unroll
        for (int j = 0; j < 4; j++) op[j] = acc[i][j] * inv;
    }
}

// ---------------- generic 128x128x8 SGEMM with epilogue ---------------------
// EPI: 0 = plain, 1 = +bias then ReLU, 2 = +residual
template <int EPI>
__global__ __launch_bounds__(256) void gemm_kernel(
    const float* __restrict__ A, const float* __restrict__ B,
    const float* __restrict__ bias, const float* __restrict__ res,
    float* __restrict__ C, int M, int N, int K)
{
    __shared__ float As[8][128];
    __shared__ float Bs[8][128];
    const int tid = threadIdx.x;
    const int tx = tid & 15, ty = tid >> 4;
    const int m0 = blockIdx.y * 128, n0 = blockIdx.x * 128;
    float acc[8][8] = {};
    const int ar  = tid >> 1;          // 0..127
    const int akq = (tid & 1) * 4;     // 0,4
    const int bkr = tid >> 5;          // 0..7
    const int bc  = (tid & 31) * 4;    // 0..124

    for (int k0 = 0; k0 < K; k0 += 8) {
        float4 av = *(const float4*)&A[(size_t)(m0 + ar) * K + k0 + akq];
        As[akq + 0][ar] = av.x; As[akq + 1][ar] = av.y;
        As[akq + 2][ar] = av.z; As[akq + 3][ar] = av.w;
        *(float4*)&Bs[bkr][bc] = *(const float4*)&B[(size_t)(k0 + bkr) * N + n0 + bc];
        __syncthreads();
        #pragma unroll
        for (int kk = 0; kk < 8; kk++) {
            float4 a0 = *(const float4*)&As[kk][ty * 8];
            float4 a1 = *(const float4*)&As[kk][ty * 8 + 4];
            float4 b0 = *(const float4*)&Bs[kk][tx * 8];
            float4 b1 = *(const float4*)&Bs[kk][tx * 8 + 4];
            float a[8] = {a0.x, a0.y, a0.z, a0.w, a1.x, a1.y, a1.z, a1.w};
            float b[8] = {b0.x, b0.y, b0.z, b0.w, b1.x, b1.y, b1.z, b1.w};
            #pragma unroll
            for (int i = 0; i < 8; i++)
                #pragma unroll
                for (int j = 0; j < 8; j++)
                    acc[i][j] += a[i] * b[j];
        }
        __syncthreads();
    }
    #pragma unroll
    for (int i = 0; i < 8; i++) {
        int r = m0 + ty * 8 + i;
        #pragma unroll
        for (int j = 0; j < 8; j++) {
            int c = n0 + tx * 8 + j;
            float v = acc[i][j];
            if (EPI == 1) { v += bias[c]; v = fmaxf(v, 0.f); }
            if (EPI == 2) { v += res[(size_t)r * N + c]; }
            C[(size_t)r * N + c] = v;
        }
    }
}

// ---------------- row LayerNorm ---------------------------------------------
__global__ __launch_bounds__(256) void ln_kernel(
    const float* __restrict__ y, const float* __restrict__ g,
    const float* __restrict__ bta, float* __restrict__ out)
{
    __shared__ float s1[256], s2[256];
    const int row = blockIdx.x;
    const float* yr = y + (size_t)row * DM;
    float v[4];
    float a = 0.f, q = 0.f;
    #pragma unroll
    for (int i = 0; i < 4; i++) {
        v[i] = yr[threadIdx.x + i * 256];
        a += v[i];
        q += v[i] * v[i];
    }
    s1[threadIdx.x] = a; s2[threadIdx.x] = q;
    __syncthreads();
    for (int st = 128; st > 0; st >>= 1) {
        if (threadIdx.x < st) {
            s1[threadIdx.x] += s1[threadIdx.x + st];
            s2[threadIdx.x] += s2[threadIdx.x + st];
        }
        __syncthreads();
    }
    const float mu = s1[0] * (1.f / DM);
    const float var = s2[0] * (1.f / DM) - mu * mu;
    const float rstd = rsqrtf(var + EPSLN);
    float* orow = out + (size_t)row * DM;
    #pragma unroll
    for (int i = 0; i < 4; i++) {
        int c = threadIdx.x + i * 256;
        orow[c] = (v[i] - mu) * rstd * g[c] + bta[c];
    }
}

// ---------------- launch ------------------------------------------------------
extern "C" void kernel_launch(void* const* d_in, const int* in_sizes, int n_in,
                              void* d_out, int out_size)
{
    const float* x   = (const float*)d_in[0];
    const float* Wq  = (const float*)d_in[1];
    const float* bq  = (const float*)d_in[2];
    const float* Wk  = (const float*)d_in[3];
    const float* bk  = (const float*)d_in[4];
    const float* Wv  = (const float*)d_in[5];
    const float* bv  = (const float*)d_in[6];
    const float* Wo  = (const float*)d_in[7];
    const float* g1  = (const float*)d_in[8];
    const float* be1 = (const float*)d_in[9];
    const float* W1  = (const float*)d_in[10];
    const float* b1f = (const float*)d_in[11];
    const float* W2  = (const float*)d_in[12];
    const float* g2  = (const float*)d_in[13];
    const float* be2 = (const float*)d_in[14];
    float* out = (float*)d_out;

    void *pQ, *pK, *pV, *pO, *py1, *ph1, *pff, *py2;
    cudaGetSymbolAddress(&pQ,  g_Q);
    cudaGetSymbolAddress(&pK,  g_K);
    cudaGetSymbolAddress(&pV,  g_V);
    cudaGetSymbolAddress(&pO,  g_O);
    cudaGetSymbolAddress(&py1, g_y1);
    cudaGetSymbolAddress(&ph1, g_h1);
    cudaGetSymbolAddress(&pff, g_ff);
    cudaGetSymbolAddress(&py2, g_y2);

    // 1) QKV projections
    qkv_kernel<<<dim3(NROWS / 128, HH, 3), 256>>>(x, Wq, bq, Wk, bk, Wv, bv);

    // 2) fused attention (flash-style)
    const size_t att_smem = (size_t)ATT_SMEM_FLOATS * sizeof(float);
    cudaFuncSetAttribute(attn_kernel, cudaFuncAttributeMaxDynamicSharedMemorySize,
                         (int)att_smem);
    attn_kernel<<<dim3(LL / BQ, BB * HH), 256, att_smem>>>(
        (float*)pO, (const float*)pQ, (const float*)pK, (const float*)pV);

    // 3) output projection + residual
    gemm_kernel<2><<<dim3(DM / 128, NROWS / 128), 256>>>(
        (const float*)pO, Wo, nullptr, x, (float*)py1, NROWS, DM, DM);

    // 4) LayerNorm 1
    ln_kernel<<<NROWS, 256>>>((const float*)py1, g1, be1, (float*)ph1);

    // 5) FFN up + bias + ReLU
    gemm_kernel<1><<<dim3(DFF / 128, NROWS / 128), 256>>>(
        (const float*)ph1, W1, b1f, nullptr, (float*)pff, NROWS, DFF, DM);

    // 6) FFN down + residual
    gemm_kernel<2><<<dim3(DM / 128, NROWS / 128), 256>>>(
        (const float*)pff, W2, nullptr, (const float*)ph1, (float*)py2, NROWS, DM, DFF);

    // 7) LayerNorm 2 -> output
    ln_kernel<<<NROWS, 256>>>((const float*)py2, g2, be2, out);
}

// round 3
// speedup vs baseline: 1.6412x; 1.6412x over previous
#include <cuda_runtime.h>
#include <cuda_bf16.h>

#define DM    1024
#define HH    16
#define DK    64
#define BB    2
#define LL    2048
#define NROWS (BB*LL)        /* 4096 */
#define DFF   4096
#define EPSLN 1e-5f
#define QKVOFF 4194304ULL    /* BB*HH*LL*DK */

typedef __nv_bfloat16 bf16;

// ---------------- scratch (device globals; no allocations allowed) ----------
__device__ float g_QKV[3ULL * QKVOFF];          // [z][b][h][l][dk] fp32
__device__ bf16  g_xhi[(size_t)NROWS * DM],  g_xlo[(size_t)NROWS * DM];
__device__ bf16  g_Wqkvh[3072ULL * 1024],    g_Wqkvl[3072ULL * 1024]; // [n=3072][k=1024]
__device__ bf16  g_Woh[1024ULL * 1024],      g_Wol[1024ULL * 1024];   // [n][k]
__device__ bf16  g_W1h[4096ULL * 1024],      g_W1l[4096ULL * 1024];   // [n=4096][k=1024]
__device__ bf16  g_W2h[1024ULL * 4096],      g_W2l[1024ULL * 4096];   // [n=1024][k=4096]
__device__ float g_bqkv[3072];
__device__ bf16  g_Ohi[(size_t)NROWS * DM],  g_Olo[(size_t)NROWS * DM];
__device__ float g_y1[(size_t)NROWS * DM];
__device__ float g_h1[(size_t)NROWS * DM];
__device__ bf16  g_h1hi[(size_t)NROWS * DM], g_h1lo[(size_t)NROWS * DM];
__device__ bf16  g_ffhi[(size_t)NROWS * DFF], g_fflo[(size_t)NROWS * DFF];
__device__ float g_y2[(size_t)NROWS * DM];

__device__ __forceinline__ void split_bf16(float v, bf16& h, bf16& l) {
    h = __float2bfloat16(v);
    l = __float2bfloat16(v - __bfloat162float(h));
}

// warp mma: D(4xf32) += A(4xb32 of bf16) * B(2xb32 of bf16)
__device__ __forceinline__ void mma16816(float* d, const unsigned* a,
                                         unsigned b0, unsigned b1) {
    asm volatile(
        "mma.sync.aligned.m16n8k16.row.col.f32.bf16.bf16.f32 "
        "{%0,%1,%2,%3}, {%4,%5,%6,%7}, {%8,%9}, {%0,%1,%2,%3};"
        : "+f"(d[0]), "+f"(d[1]), "+f"(d[2]), "+f"(d[3])
        : "r"(a[0]), "r"(a[1]), "r"(a[2]), "r"(a[3]), "r"(b0), "r"(b1));
}

// ---------------- prep kernels ----------------------------------------------
__global__ void xsplit_kernel(const float* __restrict__ x) {
    size_t i = (size_t)blockIdx.x * 1024 + threadIdx.x;
    split_bf16(x[i], g_xhi[i], g_xlo[i]);
}

__global__ void bqkv_kernel(const float* __restrict__ bq, const float* __restrict__ bk,
                            const float* __restrict__ bv) {
    int z = blockIdx.x;
    const float* s = (z == 0) ? bq : (z == 1) ? bk : bv;
    g_bqkv[z * 1024 + threadIdx.x] = s[threadIdx.x];
}

// generic transpose + split: src[K][N] -> dst[N][K] (hi/lo)
__global__ void tsplit_kernel(const float* __restrict__ src, bf16* __restrict__ dh,
                              bf16* __restrict__ dl, int K, int N) {
    __shared__ float t[32][33];
    int kb = blockIdx.y * 32, nb = blockIdx.x * 32;
    int tx = threadIdx.x, ty = threadIdx.y;
    #pragma unroll
    for (int i = 0; i < 32; i += 8)
        t[ty + i][tx] = src[(size_t)(kb + ty + i) * N + nb + tx];
    __syncthreads();
    #pragma unroll
    for (int i = 0; i < 32; i += 8) {
        float v = t[tx][ty + i];
        size_t o = (size_t)(nb + ty + i) * K + kb + tx;
        split_bf16(v, dh[o], dl[o]);
    }
}

// QKV weights: W_z[h][1024][64] -> g_Wqkv[n = z*1024 + h*64 + dk][k]
__global__ void qkvw_kernel(const float* __restrict__ Wq, const float* __restrict__ Wk,
                            const float* __restrict__ Wv) {
    __shared__ float t[32][33];
    int batch = blockIdx.z, z = batch >> 4, h = batch & 15;
    const float* src = ((z == 0) ? Wq : (z == 1) ? Wk : Wv) + (size_t)h * DM * DK;
    int kb = blockIdx.y * 32, nb = blockIdx.x * 32;
    int tx = threadIdx.x, ty = threadIdx.y;
    #pragma unroll
    for (int i = 0; i < 32; i += 8)
        t[ty + i][tx] = src[(size_t)(kb + ty + i) * DK + nb + tx];
    __syncthreads();
    #pragma unroll
    for (int i = 0; i < 32; i += 8) {
        float v = t[tx][ty + i];
        int ng = z * 1024 + h * 64 + nb + ty + i;
        size_t o = (size_t)ng * DM + kb + tx;
        split_bf16(v, g_Wqkvh[o], g_Wqkvl[o]);
    }
}

// ---------------- mma.sync bf16x3 GEMM ---------------------------------------
// C[M, N] = A[M,K] @ Bt[N,K]^T, A/B pre-split bf16 hi/lo.
// EPI 0: +bqkv, scatter into g_QKV. EPI 1: +res -> outf. EPI 2: +bias, ReLU -> hi/lo.
#define AST 40                       /* smem row stride in bf16 */
#define TILE_SZ (128 * AST)          /* 5120 bf16 per matrix tile */
#define STAGE_SZ (4 * TILE_SZ)       /* Ah, Al, Bh, Bl */
#define GEMM_SMEM (2 * STAGE_SZ * 2) /* bytes: 81920 */

template <int EPI>
__global__ __launch_bounds__(256) void gemm3_kernel(
    const bf16* __restrict__ Ahi, const bf16* __restrict__ Alo,
    const bf16* __restrict__ Bhi, const bf16* __restrict__ Blo,
    const float* __restrict__ bias, const float* __restrict__ res,
    float* __restrict__ outf, bf16* __restrict__ outhi, bf16* __restrict__ outlo,
    int K, int N)
{
    extern __shared__ bf16 smem[];
    const int tid = threadIdx.x;
    const int lane = tid & 31, wid = tid >> 5;
    const int wm = wid & 3, wn = wid >> 2;      // 4 x 2 warp grid
    const int g = lane >> 2, l2 = (lane & 3) * 2;
    const int m0 = blockIdx.y * 128, n0 = blockIdx.x * 128;
    const int nk = K >> 5;

    const int ldrow = tid >> 2;               // 0..63 (x2 chunks)
    const int ldkc  = (tid & 3) * 8;

    float d[2][8][4] = {};

    uint4 regs[8];
    // prologue: load k-step 0
    {
        size_t ga = (size_t)(m0 + ldrow) * K + ldkc;
        size_t gb = (size_t)(n0 + ldrow) * K + ldkc;
        size_t ga2 = ga + (size_t)64 * K, gb2 = gb + (size_t)64 * K;
        regs[0] = *(const uint4*)(Ahi + ga);  regs[1] = *(const uint4*)(Alo + ga);
        regs[2] = *(const uint4*)(Bhi + gb);  regs[3] = *(const uint4*)(Blo + gb);
        regs[4] = *(const uint4*)(Ahi + ga2); regs[5] = *(const uint4*)(Alo + ga2);
        regs[6] = *(const uint4*)(Bhi + gb2); regs[7] = *(const uint4*)(Blo + gb2);
        bf16* s = smem;
        int o1 = ldrow * AST + ldkc, o2 = (ldrow + 64) * AST + ldkc;
        *(uint4*)(s + o1)                = regs[0];
        *(uint4*)(s + TILE_SZ + o1)      = regs[1];
        *(uint4*)(s + 2 * TILE_SZ + o1)  = regs[2];
        *(uint4*)(s + 3 * TILE_SZ + o1)  = regs[3];
        *(uint4*)(s + o2)                = regs[4];
        *(uint4*)(s + TILE_SZ + o2)      = regs[5];
        *(uint4*)(s + 2 * TILE_SZ + o2)  = regs[6];
        *(uint4*)(s + 3 * TILE_SZ + o2)  = regs[7];
    }
    __syncthreads();

    for (int ks = 0; ks < nk; ks++) {
        if (ks + 1 < nk) {
            const int k0 = (ks + 1) << 5;
            size_t ga = (size_t)(m0 + ldrow) * K + k0 + ldkc;
            size_t gb = (size_t)(n0 + ldrow) * K + k0 + ldkc;
            size_t ga2 = ga + (size_t)64 * K, gb2 = gb + (size_t)64 * K;
            regs[0] = *(const uint4*)(Ahi + ga);  regs[1] = *(const uint4*)(Alo + ga);
            regs[2] = *(const uint4*)(Bhi + gb);  regs[3] = *(const uint4*)(Blo + gb);
            regs[4] = *(const uint4*)(Ahi + ga2); regs[5] = *(const uint4*)(Alo + ga2);
            regs[6] = *(const uint4*)(Bhi + gb2); regs[7] = *(const uint4*)(Blo + gb2);
        }

        // compute on buffer ks&1
        {
            const bf16* s   = smem + (ks & 1) * STAGE_SZ;
            const bf16* sAh = s;
            const bf16* sAl = s + TILE_SZ;
            const bf16* sBh = s + 2 * TILE_SZ;
            const bf16* sBl = s + 3 * TILE_SZ;
            #pragma unroll
            for (int kk = 0; kk < 2; kk++) {
                const int kb = kk * 16 + l2;
                unsigned ah[2][4], al[2][4];
                #pragma unroll
                for (int mt = 0; mt < 2; mt++) {
                    int r = wm * 32 + mt * 16 + g;
                    ah[mt][0] = *(const unsigned*)(sAh + r * AST + kb);
                    ah[mt][1] = *(const unsigned*)(sAh + (r + 8) * AST + kb);
                    ah[mt][2] = *(const unsigned*)(sAh + r * AST + kb + 8);
                    ah[mt][3] = *(const unsigned*)(sAh + (r + 8) * AST + kb + 8);
                    al[mt][0] = *(const unsigned*)(sAl + r * AST + kb);
                    al[mt][1] = *(const unsigned*)(sAl + (r + 8) * AST + kb);
                    al[mt][2] = *(const unsigned*)(sAl + r * AST + kb + 8);
                    al[mt][3] = *(const unsigned*)(sAl + (r + 8) * AST + kb + 8);
                }
                #pragma unroll
                for (int nt = 0; nt < 8; nt++) {
                    int nr = wn * 64 + nt * 8 + g;
                    unsigned bh0 = *(const unsigned*)(sBh + nr * AST + kb);
                    unsigned bh1 = *(const unsigned*)(sBh + nr * AST + kb + 8);
                    unsigned bl0 = *(const unsigned*)(sBl + nr * AST + kb);
                    unsigned bl1 = *(const unsigned*)(sBl + nr * AST + kb + 8);
                    #pragma unroll
                    for (int mt = 0; mt < 2; mt++) {
                        mma16816(d[mt][nt], ah[mt], bh0, bh1);
                        mma16816(d[mt][nt], ah[mt], bl0, bl1);
                        mma16816(d[mt][nt], al[mt], bh0, bh1);
                    }
                }
            }
        }

        if (ks + 1 < nk) {
            bf16* s = smem + ((ks + 1) & 1) * STAGE_SZ;
            int o1 = ldrow * AST + ldkc, o2 = (ldrow + 64) * AST + ldkc;
            *(uint4*)(s + o1)                = regs[0];
            *(uint4*)(s + TILE_SZ + o1)      = regs[1];
            *(uint4*)(s + 2 * TILE_SZ + o1)  = regs[2];
            *(uint4*)(s + 3 * TILE_SZ + o1)  = regs[3];
            *(uint4*)(s + o2)                = regs[4];
            *(uint4*)(s + TILE_SZ + o2)      = regs[5];
            *(uint4*)(s + 2 * TILE_SZ + o2)  = regs[6];
            *(uint4*)(s + 3 * TILE_SZ + o2)  = regs[7];
        }
        __syncthreads();
    }

    // ---- epilogue: fragment rows g, g+8; cols l2, l2+1 of each 16x8 tile ----
    #pragma unroll
    for (int mt = 0; mt < 2; mt++) {
        #pragma unroll
        for (int nt = 0; nt < 8; nt++) {
            int rbase = m0 + wm * 32 + mt * 16 + g;
            int cc = n0 + wn * 64 + nt * 8 + l2;
            #pragma unroll
            for (int rr = 0; rr < 2; rr++) {
                int rg = rbase + rr * 8;
                float v0 = d[mt][nt][rr * 2 + 0];
                float v1 = d[mt][nt][rr * 2 + 1];
                if (EPI == 0) {
                    float2 bv = *(const float2*)(bias + cc);
                    int z = cc >> 10, h = (cc >> 6) & 15, dk = cc & 63;
                    int bb_ = rg >> 11, lpos = rg & 2047;
                    float* op = outf + (size_t)z * QKVOFF +
                                (((size_t)(bb_ * 16 + h) * 2048 + lpos) << 6) + dk;
                    *(float2*)op = make_float2(v0 + bv.x, v1 + bv.y);
                } else if (EPI == 1) {
                    size_t o = (size_t)rg * N + cc;
                    float2 rv = *(const float2*)(res + o);
                    *(float2*)(outf + o) = make_float2(v0 + rv.x, v1 + rv.y);
                } else {
                    size_t o = (size_t)rg * N + cc;
                    float2 bv = *(const float2*)(bias + cc);
                    float w0 = fmaxf(v0 + bv.x, 0.f);
                    float w1 = fmaxf(v1 + bv.y, 0.f);
                    bf16 h0, l0, h1b, l1;
                    split_bf16(w0, h0, l0);
                    split_bf16(w1, h1b, l1);
                    *(__nv_bfloat162*)(outhi + o) = __nv_bfloat162(h0, h1b);
                    *(__nv_bfloat162*)(outlo + o) = __nv_bfloat162(l0, l1);
                }
            }
        }
    }
}

// ---------------- fused flash attention (fp32) ------------------------------
#define BQ  128
#define BKT 128
#define QST 132
#define VST 68
#define PST 132
#define RST 17
#define ATT_SMEM_FLOATS (64*QST + 64*QST + 128*VST + 128*PST + 128*RST + 128 + 128)

__global__ __launch_bounds__(256) void attn_kernel(const float* __restrict__ QKV)
{
    extern __shared__ float sm[];
    float* Qst = sm;
    float* Kst = Qst + 64 * QST;
    float* Vs  = Kst + 64 * QST;
    float* Ps  = Vs  + 128 * VST;
    float* red = Ps  + 128 * PST;
    float* m_s = red + 128 * RST;
    float* l_s = m_s + 128;

    const float* Q = QKV;
    const float* K = QKV + QKVOFF;
    const float* V = QKV + 2 * QKVOFF;

    const int tid = threadIdx.x;
    const int tx = tid & 15, ty = tid >> 4;
    const int bh = blockIdx.y, qt = blockIdx.x;
    const float* Qp = Q + (size_t)bh * LL * DK + (size_t)qt * BQ * DK;
    const float* Kb = K + (size_t)bh * LL * DK;
    const float* Vb = V + (size_t)bh * LL * DK;

    for (int idx = tid; idx < BQ * DK; idx += 256) {
        int r = idx >> 6, c = idx & 63;
        Qst[c * QST + r] = Qp[idx] * 0.125f;
    }
    if (tid < 128) { m_s[tid] = -1e30f; l_s[tid] = 0.f; }
    float acc[8][4] = {};
    __syncthreads();

    for (int kt = 0; kt < LL / BKT; kt++) {
        const float* Kp = Kb + (size_t)kt * BKT * DK;
        const float* Vp = Vb + (size_t)kt * BKT * DK;
        for (int idx = tid; idx < BKT * DK; idx += 256) {
            int r = idx >> 6, c = idx & 63;
            Kst[c * QST + r] = Kp[idx];
            Vs[r * VST + c]  = Vp[idx];
        }
        __syncthreads();

        float s[8][8] = {};
        #pragma unroll 8
        for (int kk = 0; kk < DK; kk++) {
            float4 qa = *(const float4*)&Qst[kk * QST + ty * 8];
            float4 qb = *(const float4*)&Qst[kk * QST + ty * 8 + 4];
            float4 ka = *(const float4*)&Kst[kk * QST + tx * 8];
            float4 kb = *(const float4*)&Kst[kk * QST + tx * 8 + 4];
            float a[8] = {qa.x, qa.y, qa.z, qa.w, qb.x, qb.y, qb.z, qb.w};
            float b[8] = {ka.x, ka.y, ka.z, ka.w, kb.x, kb.y, kb.z, kb.w};
            #pragma unroll
            for (int i = 0; i < 8; i++)
                #pragma unroll
                for (int j = 0; j < 8; j++)
                    s[i][j] += a[i] * b[j];
        }

        float m_old[8], m_new[8], alpha[8], rs[8];
        #pragma unroll
        for (int i = 0; i < 8; i++) {
            int row = ty * 8 + i;
            float rm = s[i][0];
            #pragma unroll
            for (int j = 1; j < 8; j++) rm = fmaxf(rm, s[i][j]);
            red[row * RST + tx] = rm;
            m_old[i] = m_s[row];
        }
        __syncthreads();
        #pragma unroll
        for (int i = 0; i < 8; i++) {
            int row = ty * 8 + i;
            float tm = red[row * RST];
            #pragma unroll
            for (int t = 1; t < 16; t++) tm = fmaxf(tm, red[row * RST + t]);
            m_new[i] = fmaxf(m_old[i], tm);
            alpha[i] = __expf(m_old[i] - m_new[i]);
            float sum = 0.f;
            #pragma unroll
            for (int j = 0; j < 8; j++) {
                s[i][j] = __expf(s[i][j] - m_new[i]);
                sum += s[i][j];
            }
            rs[i] = sum;
        }
        __syncthreads();
        #pragma unroll
        for (int i = 0; i < 8; i++) red[(ty * 8 + i) * RST + tx] = rs[i];
        __syncthreads();
        #pragma unroll
        for (int i = 0; i < 8; i++) {
            int row = ty * 8 + i;
            if (tx == 0) {
                float ts = 0.f;
                #pragma unroll
                for (int t = 0; t < 16; t++) ts += red[row * RST + t];
                l_s[row] = l_s[row] * alpha[i] + ts;
                m_s[row] = m_new[i];
            }
            #pragma unroll
            for (int j = 0; j < 4; j++) acc[i][j] *= alpha[i];
            *(float4*)&Ps[row * PST + tx * 8]     = make_float4(s[i][0], s[i][1], s[i][2], s[i][3]);
            *(float4*)&Ps[row * PST + tx * 8 + 4] = make_float4(s[i][4], s[i][5], s[i][6], s[i][7]);
        }
        __syncthreads();

        for (int k4 = 0; k4 < BKT; k4 += 4) {
            float4 v0 = *(const float4*)&Vs[(k4 + 0) * VST + tx * 4];
            float4 v1 = *(const float4*)&Vs[(k4 + 1) * VST + tx * 4];
            float4 v2 = *(const float4*)&Vs[(k4 + 2) * VST + tx * 4];
            float4 v3 = *(const float4*)&Vs[(k4 + 3) * VST + tx * 4];
            #pragma unroll
            for (int i = 0; i < 8; i++) {
                float4 p = *(const float4*)&Ps[(ty * 8 + i) * PST + k4];
                acc[i][0] += p.x * v0.x + p.y * v1.x + p.z * v2.x + p.w * v3.x;
                acc[i][1] += p.x * v0.y + p.y * v1.y + p.z * v2.y + p.w * v3.y;
                acc[i][2] += p.x * v0.z + p.y * v1.z + p.z * v2.z + p.w * v3.z;
                acc[i][3] += p.x * v0.w + p.y * v1.w + p.z * v2.w + p.w * v3.w;
            }
        }
        __syncthreads();
    }

    const int b = bh >> 4, h = bh & 15;
    #pragma unroll
    for (int i = 0; i < 8; i++) {
        int row = ty * 8 + i;
        float inv = 1.f / l_s[row];
        size_t nrow = (size_t)b * LL + (size_t)qt * BQ + row;
        size_t o = nrow * DM + h * DK + tx * 4;
        #pragma unroll
        for (int j = 0; j < 4; j++) {
            float v = acc[i][j] * inv;
            split_bf16(v, g_Ohi[o + j], g_Olo[o + j]);
        }
    }
}

// ---------------- row LayerNorm (optionally emits bf16 hi/lo split) ---------
template <bool SPLIT>
__global__ __launch_bounds__(256) void ln_kernel(
    const float* __restrict__ y, const float* __restrict__ g,
    const float* __restrict__ bta, float* __restrict__ out,
    bf16* __restrict__ outhi, bf16* __restrict__ outlo)
{
    __shared__ float s1[256], s2[256];
    const int row = blockIdx.x;
    const float* yr = y + (size_t)row * DM;
    float v[4];
    float a = 0.f, q = 0.f;
    #pragma unroll
    for (int i = 0; i < 4; i++) {
        v[i] = yr[threadIdx.x + i * 256];
        a += v[i]; q += v[i] * v[i];
    }
    s1[threadIdx.x] = a; s2[threadIdx.x] = q;
    __syncthreads();
    for (int st = 128; st > 0; st >>= 1) {
        if (threadIdx.x < st) {
            s1[threadIdx.x] += s1[threadIdx.x + st];
            s2[threadIdx.x] += s2[threadIdx.x + st];
        }
        __syncthreads();
    }
    const float mu = s1[0] * (1.f / DM);
    const float var = s2[0] * (1.f / DM) - mu * mu;
    const float rstd = rsqrtf(var + EPSLN);
    #pragma unroll
    for (int i = 0; i < 4; i++) {
        int c = threadIdx.x + i * 256;
        size_t o = (size_t)row * DM + c;
        float ov = (v[i] - mu) * rstd * g[c] + bta[c];
        out[o] = ov;
        if (SPLIT) split_bf16(ov, outhi[o], outlo[o]);
    }
}

// ---------------- launch ------------------------------------------------------
extern "C" void kernel_launch(void* const* d_in, const int* in_sizes, int n_in,
                              void* d_out, int out_size)
{
    const float* x   = (const float*)d_in[0];
    const float* Wq  = (const float*)d_in[1];
    const float* bq  = (const float*)d_in[2];
    const float* Wk  = (const float*)d_in[3];
    const float* bk  = (const float*)d_in[4];
    const float* Wv  = (const float*)d_in[5];
    const float* bv  = (const float*)d_in[6];
    const float* Wo  = (const float*)d_in[7];
    const float* g1  = (const float*)d_in[8];
    const float* be1 = (const float*)d_in[9];
    const float* W1  = (const float*)d_in[10];
    const float* b1f = (const float*)d_in[11];
    const float* W2  = (const float*)d_in[12];
    const float* g2  = (const float*)d_in[13];
    const float* be2 = (const float*)d_in[14];
    float* out = (float*)d_out;

    void *pQKV, *pxh, *pxl, *pWqh, *pWql, *pWoh, *pWol, *pW1h, *pW1l, *pW2h, *pW2l;
    void *pbq, *pOh, *pOl, *py1, *ph1, *ph1h, *ph1l, *pffh, *pffl, *py2;
    cudaGetSymbolAddress(&pQKV, g_QKV);
    cudaGetSymbolAddress(&pxh, g_xhi);   cudaGetSymbolAddress(&pxl, g_xlo);
    cudaGetSymbolAddress(&pWqh, g_Wqkvh); cudaGetSymbolAddress(&pWql, g_Wqkvl);
    cudaGetSymbolAddress(&pWoh, g_Woh);  cudaGetSymbolAddress(&pWol, g_Wol);
    cudaGetSymbolAddress(&pW1h, g_W1h);  cudaGetSymbolAddress(&pW1l, g_W1l);
    cudaGetSymbolAddress(&pW2h, g_W2h);  cudaGetSymbolAddress(&pW2l, g_W2l);
    cudaGetSymbolAddress(&pbq, g_bqkv);
    cudaGetSymbolAddress(&pOh, g_Ohi);   cudaGetSymbolAddress(&pOl, g_Olo);
    cudaGetSymbolAddress(&py1, g_y1);    cudaGetSymbolAddress(&ph1, g_h1);
    cudaGetSymbolAddress(&ph1h, g_h1hi); cudaGetSymbolAddress(&ph1l, g_h1lo);
    cudaGetSymbolAddress(&pffh, g_ffhi); cudaGetSymbolAddress(&pffl, g_fflo);
    cudaGetSymbolAddress(&py2, g_y2);

    cudaFuncSetAttribute(gemm3_kernel<0>, cudaFuncAttributeMaxDynamicSharedMemorySize, GEMM_SMEM);
    cudaFuncSetAttribute(gemm3_kernel<1>, cudaFuncAttributeMaxDynamicSharedMemorySize, GEMM_SMEM);
    cudaFuncSetAttribute(gemm3_kernel<2>, cudaFuncAttributeMaxDynamicSharedMemorySize, GEMM_SMEM);
    const size_t att_smem = (size_t)ATT_SMEM_FLOATS * sizeof(float);
    cudaFuncSetAttribute(attn_kernel, cudaFuncAttributeMaxDynamicSharedMemorySize, (int)att_smem);

    // ---- prep: splits + transposed/split weights
    xsplit_kernel<<<NROWS, 1024>>>(x);
    qkvw_kernel<<<dim3(2, 32, 48), dim3(32, 8)>>>(Wq, Wk, Wv);
    bqkv_kernel<<<3, 1024>>>(bq, bk, bv);
    tsplit_kernel<<<dim3(32, 32),  dim3(32, 8)>>>(Wo, (bf16*)pWoh, (bf16*)pWol, 1024, 1024);
    tsplit_kernel<<<dim3(128, 32), dim3(32, 8)>>>(W1, (bf16*)pW1h, (bf16*)pW1l, 1024, 4096);
    tsplit_kernel<<<dim3(32, 128), dim3(32, 8)>>>(W2, (bf16*)pW2h, (bf16*)pW2l, 4096, 1024);

    // ---- 1) QKV projection (scatter epilogue)
    gemm3_kernel<0><<<dim3(24, 32), 256, GEMM_SMEM>>>(
        (const bf16*)pxh, (const bf16*)pxl, (const bf16*)pWqh, (const bf16*)pWql,
        (const float*)pbq, nullptr, (float*)pQKV, nullptr, nullptr, 1024, 3072);

    // ---- 2) attention (fp32, writes split O)
    attn_kernel<<<dim3(LL / BQ, BB * HH), 256, att_smem>>>((const float*)pQKV);

    // ---- 3) O-proj + residual x -> y1
    gemm3_kernel<1><<<dim3(8, 32), 256, GEMM_SMEM>>>(
        (const bf16*)pOh, (const bf16*)pOl, (const bf16*)pWoh, (const bf16*)pWol,
        nullptr, x, (float*)py1, nullptr, nullptr, 1024, 1024);

    // ---- 4) LayerNorm 1 (emits fp32 + split)
    ln_kernel<true><<<NROWS, 256>>>((const float*)py1, g1, be1,
                                    (float*)ph1, (bf16*)ph1h, (bf16*)ph1l);

    // ---- 5) FFN up + bias + ReLU -> split ff
    gemm3_kernel<2><<<dim3(32, 32), 256, GEMM_SMEM>>>(
        (const bf16*)ph1h, (const bf16*)ph1l, (const bf16*)pW1h, (const bf16*)pW1l,
        b1f, nullptr, nullptr, (bf16*)pffh, (bf16*)pffl, 1024, 4096);

    // ---- 6) FFN down + residual h1 -> y2
    gemm3_kernel<1><<<dim3(8, 32), 256, GEMM_SMEM>>>(
        (const bf16*)pffh, (const bf16*)pffl, (const bf16*)pW2h, (const bf16*)pW2l,
        nullptr, (const float*)ph1, (float*)py2, nullptr, nullptr, 4096, 1024);

    // ---- 7) LayerNorm 2 -> output
    ln_kernel<false><<<NROWS, 256>>>((const float*)py2, g2, be2, out, nullptr, nullptr);
}

// round 4
// speedup vs baseline: 2.8819x; 1.7559x over previous
#include <cuda_runtime.h>
#include <cuda_bf16.h>

#define DM    1024
#define HH    16
#define DK    64
#define BB    2
#define LL    2048
#define NROWS (BB*LL)        /* 4096 */
#define DFF   4096
#define EPSLN 1e-5f
#define HEADS (BB*HH)

typedef __nv_bfloat16 bf16;

// scale for Q: 1/sqrt(64) * log2(e) so softmax can use exp2
#define QSCL 0.18033688011112042f

// ---------------- scratch (device globals; no allocations allowed) ----------
__device__ bf16  g_xhi[(size_t)NROWS * DM],  g_xlo[(size_t)NROWS * DM];
__device__ bf16  g_Wqkvh[3072ULL * 1024],    g_Wqkvl[3072ULL * 1024]; // [n=3072][k=1024]
__device__ bf16  g_Woh[1024ULL * 1024],      g_Wol[1024ULL * 1024];   // [n][k]
__device__ bf16  g_W1h[4096ULL * 1024],      g_W1l[4096ULL * 1024];   // [n=4096][k=1024]
__device__ bf16  g_W2h[1024ULL * 4096],      g_W2l[1024ULL * 4096];   // [n=1024][k=4096]
__device__ float g_bqkv[3072];
__device__ bf16  g_Qb[(size_t)HEADS * LL * DK];   // [bh][l][dk], pre-scaled
__device__ bf16  g_Kb[(size_t)HEADS * LL * DK];   // [bh][l][dk]
__device__ bf16  g_Vt[(size_t)HEADS * DK * LL];   // [bh][dk][l]  (transposed)
__device__ bf16  g_Ohi[(size_t)NROWS * DM],  g_Olo[(size_t)NROWS * DM];
__device__ float g_y1[(size_t)NROWS * DM];
__device__ float g_h1[(size_t)NROWS * DM];
__device__ bf16  g_h1hi[(size_t)NROWS * DM], g_h1lo[(size_t)NROWS * DM];
__device__ bf16  g_ffhi[(size_t)NROWS * DFF], g_fflo[(size_t)NROWS * DFF];
__device__ float g_y2[(size_t)NROWS * DM];

__device__ __forceinline__ void split_bf16(float v, bf16& h, bf16& l) {
    h = __float2bfloat16(v);
    l = __float2bfloat16(v - __bfloat162float(h));
}

__device__ __forceinline__ void mma16816(float* d, const unsigned* a,
                                         unsigned b0, unsigned b1) {
    asm volatile(
        "mma.sync.aligned.m16n8k16.row.col.f32.bf16.bf16.f32 "
        "{%0,%1,%2,%3}, {%4,%5,%6,%7}, {%8,%9}, {%0,%1,%2,%3};"
        : "+f"(d[0]), "+f"(d[1]), "+f"(d[2]), "+f"(d[3])
        : "r"(a[0]), "r"(a[1]), "r"(a[2]), "r"(a[3]), "r"(b0), "r"(b1));
}
__device__ __forceinline__ unsigned smem_u32(const void* p) {
    unsigned a;
    asm("{ .reg .u64 t; cvta.to.shared.u64 t, %1; cvt.u32.u64 %0, t; }"
        : "=r"(a) : "l"(p));
    return a;
}
__device__ __forceinline__ float ex2f(float x) {
    float y; asm("ex2.approx.f32 %0, %1;" : "=f"(y) : "f"(x)); return y;
}
__device__ __forceinline__ unsigned packbf2(float lo, float hi) {
    unsigned r; asm("cvt.rn.bf16x2.f32 %0, %1, %2;" : "=r"(r) : "f"(hi), "f"(lo));
    return r;
}
__device__ __forceinline__ void ldmx4(unsigned& r0, unsigned& r1, unsigned& r2,
                                      unsigned& r3, unsigned addr) {
    asm volatile("ldmatrix.sync.aligned.m8n8.x4.shared.b16 {%0,%1,%2,%3}, [%4];"
                 : "=r"(r0), "=r"(r1), "=r"(r2), "=r"(r3) : "r"(addr));
}
__device__ __forceinline__ void cp16(unsigned dst, const void* src) {
    asm volatile("cp.async.cg.shared.global [%0], [%1], 16;" :: "r"(dst), "l"(src));
}
__device__ __forceinline__ void cp_commit() {
    asm volatile("cp.async.commit_group;" ::: "memory");
}
template <int N>
__device__ __forceinline__ void cp_wait() {
    asm volatile("cp.async.wait_group %0;" :: "n"(N) : "memory");
}

// ---------------- prep kernels ----------------------------------------------
__global__ void xsplit_kernel(const float* __restrict__ x) {
    size_t i = (size_t)blockIdx.x * 1024 + threadIdx.x;
    split_bf16(x[i], g_xhi[i], g_xlo[i]);
}
__global__ void bqkv_kernel(const float* __restrict__ bq, const float* __restrict__ bk,
                            const float* __restrict__ bv) {
    int z = blockIdx.x;
    const float* s = (z == 0) ? bq : (z == 1) ? bk : bv;
    g_bqkv[z * 1024 + threadIdx.x] = s[threadIdx.x];
}
__global__ void tsplit_kernel(const float* __restrict__ src, bf16* __restrict__ dh,
                              bf16* __restrict__ dl, int K, int N) {
    __shared__ float t[32][33];
    int kb = blockIdx.y * 32, nb = blockIdx.x * 32;
    int tx = threadIdx.x, ty = threadIdx.y;
    #pragma unroll
    for (int i = 0; i < 32; i += 8)
        t[ty + i][tx] = src[(size_t)(kb + ty + i) * N + nb + tx];
    __syncthreads();
    #pragma unroll
    for (int i = 0; i < 32; i += 8) {
        float v = t[tx][ty + i];
        size_t o = (size_t)(nb + ty + i) * K + kb + tx;
        split_bf16(v, dh[o], dl[o]);
    }
}
__global__ void qkvw_kernel(const float* __restrict__ Wq, const float* __restrict__ Wk,
                            const float* __restrict__ Wv) {
    __shared__ float t[32][33];
    int batch = blockIdx.z, z = batch >> 4, h = batch & 15;
    const float* src = ((z == 0) ? Wq : (z == 1) ? Wk : Wv) + (size_t)h * DM * DK;
    int kb = blockIdx.y * 32, nb = blockIdx.x * 32;
    int tx = threadIdx.x, ty = threadIdx.y;
    #pragma unroll
    for (int i = 0; i < 32; i += 8)
        t[ty + i][tx] = src[(size_t)(kb + ty + i) * DK + nb + tx];
    __syncthreads();
    #pragma unroll
    for (int i = 0; i < 32; i += 8) {
        float v = t[tx][ty + i];
        int ng = z * 1024 + h * 64 + nb + ty + i;
        size_t o = (size_t)ng * DM + kb + tx;
        split_bf16(v, g_Wqkvh[o], g_Wqkvl[o]);
    }
}

// ---------------- mma.sync bf16x3 GEMM ---------------------------------------
#define AST 40
#define TILE_SZ (128 * AST)
#define STAGE_SZ (4 * TILE_SZ)
#define GEMM_SMEM (2 * STAGE_SZ * 2)

template <int EPI>
__global__ __launch_bounds__(256) void gemm3_kernel(
    const bf16* __restrict__ Ahi, const bf16* __restrict__ Alo,
    const bf16* __restrict__ Bhi, const bf16* __restrict__ Blo,
    const float* __restrict__ bias, const float* __restrict__ res,
    float* __restrict__ outf, bf16* __restrict__ outhi, bf16* __restrict__ outlo,
    int K, int N)
{
    extern __shared__ bf16 smem[];
    const int tid = threadIdx.x;
    const int lane = tid & 31, wid = tid >> 5;
    const int wm = wid & 3, wn = wid >> 2;
    const int g = lane >> 2, l2 = (lane & 3) * 2;
    const int m0 = blockIdx.y * 128, n0 = blockIdx.x * 128;
    const int nk = K >> 5;
    const int ldrow = tid >> 2;
    const int ldkc  = (tid & 3) * 8;

    float d[2][8][4] = {};
    uint4 regs[8];
    {
        size_t ga = (size_t)(m0 + ldrow) * K + ldkc;
        size_t gb = (size_t)(n0 + ldrow) * K + ldkc;
        size_t ga2 = ga + (size_t)64 * K, gb2 = gb + (size_t)64 * K;
        regs[0] = *(const uint4*)(Ahi + ga);  regs[1] = *(const uint4*)(Alo + ga);
        regs[2] = *(const uint4*)(Bhi + gb);  regs[3] = *(const uint4*)(Blo + gb);
        regs[4] = *(const uint4*)(Ahi + ga2); regs[5] = *(const uint4*)(Alo + ga2);
        regs[6] = *(const uint4*)(Bhi + gb2); regs[7] = *(const uint4*)(Blo + gb2);
        bf16* s = smem;
        int o1 = ldrow * AST + ldkc, o2 = (ldrow + 64) * AST + ldkc;
        *(uint4*)(s + o1)                = regs[0];
        *(uint4*)(s + TILE_SZ + o1)      = regs[1];
        *(uint4*)(s + 2 * TILE_SZ + o1)  = regs[2];
        *(uint4*)(s + 3 * TILE_SZ + o1)  = regs[3];
        *(uint4*)(s + o2)                = regs[4];
        *(uint4*)(s + TILE_SZ + o2)      = regs[5];
        *(uint4*)(s + 2 * TILE_SZ + o2)  = regs[6];
        *(uint4*)(s + 3 * TILE_SZ + o2)  = regs[7];
    }
    __syncthreads();

    for (int ks = 0; ks < nk; ks++) {
        if (ks + 1 < nk) {
            const int k0 = (ks + 1) << 5;
            size_t ga = (size_t)(m0 + ldrow) * K + k0 + ldkc;
            size_t gb = (size_t)(n0 + ldrow) * K + k0 + ldkc;
            size_t ga2 = ga + (size_t)64 * K, gb2 = gb + (size_t)64 * K;
            regs[0] = *(const uint4*)(Ahi + ga);  regs[1] = *(const uint4*)(Alo + ga);
            regs[2] = *(const uint4*)(Bhi + gb);  regs[3] = *(const uint4*)(Blo + gb);
            regs[4] = *(const uint4*)(Ahi + ga2); regs[5] = *(const uint4*)(Alo + ga2);
            regs[6] = *(const uint4*)(Bhi + gb2); regs[7] = *(const uint4*)(Blo + gb2);
        }
        {
            const bf16* s   = smem + (ks & 1) * STAGE_SZ;
            const bf16* sAh = s;
            const bf16* sAl = s + TILE_SZ;
            const bf16* sBh = s + 2 * TILE_SZ;
            const bf16* sBl = s + 3 * TILE_SZ;
            #pragma unroll
            for (int kk = 0; kk < 2; kk++) {
                const int kb = kk * 16 + l2;
                unsigned ah[2][4], al[2][4];
                #pragma unroll
                for (int mt = 0; mt < 2; mt++) {
                    int r = wm * 32 + mt * 16 + g;
                    ah[mt][0] = *(const unsigned*)(sAh + r * AST + kb);
                    ah[mt][1] = *(const unsigned*)(sAh + (r + 8) * AST + kb);
                    ah[mt][2] = *(const unsigned*)(sAh + r * AST + kb + 8);
                    ah[mt][3] = *(const unsigned*)(sAh + (r + 8) * AST + kb + 8);
                    al[mt][0] = *(const unsigned*)(sAl + r * AST + kb);
                    al[mt][1] = *(const unsigned*)(sAl + (r + 8) * AST + kb);
                    al[mt][2] = *(const unsigned*)(sAl + r * AST + kb + 8);
                    al[mt][3] = *(const unsigned*)(sAl + (r + 8) * AST + kb + 8);
                }
                #pragma unroll
                for (int nt = 0; nt < 8; nt++) {
                    int nr = wn * 64 + nt * 8 + g;
                    unsigned bh0 = *(const unsigned*)(sBh + nr * AST + kb);
                    unsigned bh1 = *(const unsigned*)(sBh + nr * AST + kb + 8);
                    unsigned bl0 = *(const unsigned*)(sBl + nr * AST + kb);
                    unsigned bl1 = *(const unsigned*)(sBl + nr * AST + kb + 8);
                    #pragma unroll
                    for (int mt = 0; mt < 2; mt++) {
                        mma16816(d[mt][nt], ah[mt], bh0, bh1);
                        mma16816(d[mt][nt], ah[mt], bl0, bl1);
                        mma16816(d[mt][nt], al[mt], bh0, bh1);
                    }
                }
            }
        }
        if (ks + 1 < nk) {
            bf16* s = smem + ((ks + 1) & 1) * STAGE_SZ;
            int o1 = ldrow * AST + ldkc, o2 = (ldrow + 64) * AST + ldkc;
            *(uint4*)(s + o1)                = regs[0];
            *(uint4*)(s + TILE_SZ + o1)      = regs[1];
            *(uint4*)(s + 2 * TILE_SZ + o1)  = regs[2];
            *(uint4*)(s + 3 * TILE_SZ + o1)  = regs[3];
            *(uint4*)(s + o2)                = regs[4];
            *(uint4*)(s + TILE_SZ + o2)      = regs[5];
            *(uint4*)(s + 2 * TILE_SZ + o2)  = regs[6];
            *(uint4*)(s + 3 * TILE_SZ + o2)  = regs[7];
        }
        __syncthreads();
    }

    #pragma unroll
    for (int mt = 0; mt < 2; mt++) {
        #pragma unroll
        for (int nt = 0; nt < 8; nt++) {
            int rbase = m0 + wm * 32 + mt * 16 + g;
            int cc = n0 + wn * 64 + nt * 8 + l2;
            #pragma unroll
            for (int rr = 0; rr < 2; rr++) {
                int rg = rbase + rr * 8;
                float v0 = d[mt][nt][rr * 2 + 0];
                float v1 = d[mt][nt][rr * 2 + 1];
                if (EPI == 0) {
                    // QKV epilogue: bf16 Q (scaled), K, V^T
                    float2 bv = *(const float2*)(bias + cc);
                    float w0 = v0 + bv.x, w1 = v1 + bv.y;
                    int z = cc >> 10, h = (cc >> 6) & 15, dk = cc & 63;
                    int bb_ = rg >> 11, lpos = rg & 2047;
                    size_t headbase = (size_t)(bb_ * 16 + h);
                    if (z == 0) {
                        w0 *= QSCL; w1 *= QSCL;
                        *(__nv_bfloat162*)(g_Qb + (headbase * 2048 + lpos) * 64 + dk) =
                            __nv_bfloat162(__float2bfloat16(w0), __float2bfloat16(w1));
                    } else if (z == 1) {
                        *(__nv_bfloat162*)(g_Kb + (headbase * 2048 + lpos) * 64 + dk) =
                            __nv_bfloat162(__float2bfloat16(w0), __float2bfloat16(w1));
                    } else {
                        size_t vb = (headbase * 64 + dk) * 2048 + lpos;
                        g_Vt[vb] = __float2bfloat16(w0);
                        g_Vt[vb + 2048] = __float2bfloat16(w1);
                    }
                } else if (EPI == 1) {
                    size_t o = (size_t)rg * N + cc;
                    float2 rv = *(const float2*)(res + o);
                    *(float2*)(outf + o) = make_float2(v0 + rv.x, v1 + rv.y);
                } else {
                    size_t o = (size_t)rg * N + cc;
                    float2 bv = *(const float2*)(bias + cc);
                    float w0 = fmaxf(v0 + bv.x, 0.f);
                    float w1 = fmaxf(v1 + bv.y, 0.f);
                    bf16 h0, l0, h1b, l1;
                    split_bf16(w0, h0, l0);
                    split_bf16(w1, h1b, l1);
                    *(__nv_bfloat162*)(outhi + o) = __nv_bfloat162(h0, h1b);
                    *(__nv_bfloat162*)(outlo + o) = __nv_bfloat162(l0, l1);
                }
            }
        }
    }
}

// ---------------- bf16 tensor-core flash attention ---------------------------
#define KST 72            /* K/Q smem row stride (bf16) */
#define VST 136           /* Vt smem row stride (bf16) */
#define QS_SZ   (128 * KST)
#define KT_SZ   (128 * KST)
#define VT_SZ   (64 * VST)
#define BUF_SZ  (KT_SZ + VT_SZ)
#define ATTN_SMEM ((QS_SZ + 2 * BUF_SZ) * 2)   /* bytes */

__global__ __launch_bounds__(256, 1) void attn_kernel()
{
    extern __shared__ bf16 sm[];
    bf16* Qs = sm;
    const int tid = threadIdx.x, lane = tid & 31, w = tid >> 5;
    const int g = lane >> 2, t = lane & 3;
    const int qt = blockIdx.x, bh = blockIdx.y;
    const int bI = bh >> 4, h = bh & 15;

    const bf16* Qg = g_Qb + ((size_t)bh * LL + qt * 128) * 64;
    const bf16* Kg = g_Kb + (size_t)bh * LL * 64;
    const bf16* Vg = g_Vt + (size_t)bh * 64 * LL;
    const unsigned smb = smem_u32(sm);

    // stage Q (plain loads)
    #pragma unroll
    for (int i = 0; i < 4; i++) {
        int c = tid + i * 256;
        int r = c >> 3, cc = (c & 7) * 8;
        *(uint4*)(Qs + r * KST + cc) = *(const uint4*)(Qg + r * 64 + cc);
    }

    // prefetch tile 0 via cp.async
    {
        unsigned kbase = smb + QS_SZ * 2;
        unsigned vbase = kbase + KT_SZ * 2;
        #pragma unroll
        for (int i = 0; i < 4; i++) {
            int c = tid + i * 256;
            int r = c >> 3, cc = (c & 7) * 8;
            cp16(kbase + (r * KST + cc) * 2, Kg + r * 64 + cc);
        }
        #pragma unroll
        for (int i = 0; i < 4; i++) {
            int c = tid + i * 256;
            int r = c >> 4, cc = (c & 15) * 8;
            cp16(vbase + (r * VST + cc) * 2, Vg + (size_t)r * LL + cc);
        }
        cp_commit();
    }
    __syncthreads();

    // Q fragments (16x64 per warp)
    unsigned qa[4][4];
    {
        const int qrow = w * 16 + g;
        #pragma unroll
        for (int kk = 0; kk < 4; kk++) {
            qa[kk][0] = *(const unsigned*)(Qs + qrow * KST + kk * 16 + 2 * t);
            qa[kk][1] = *(const unsigned*)(Qs + (qrow + 8) * KST + kk * 16 + 2 * t);
            qa[kk][2] = *(const unsigned*)(Qs + qrow * KST + kk * 16 + 8 + 2 * t);
            qa[kk][3] = *(const unsigned*)(Qs + (qrow + 8) * KST + kk * 16 + 8 + 2 * t);
        }
    }

    float m0 = -1e30f, m1 = -1e30f, l0 = 0.f, l1 = 0.f;
    float o[8][4] = {};

    // ldmatrix per-lane address components
    const int lrow = lane & 7;
    const int lh8  = ((lane >> 3) & 1) << 3;
    const int ln8  = (lane >> 4) << 3;

    for (int kt = 0; kt < 16; kt++) {
        // prefetch next tile
        if (kt + 1 < 16) {
            int nb = (kt + 1) & 1;
            unsigned kbase = smb + (QS_SZ + nb * BUF_SZ) * 2;
            unsigned vbase = kbase + KT_SZ * 2;
            const bf16* Kp = Kg + (size_t)(kt + 1) * 128 * 64;
            #pragma unroll
            for (int i = 0; i < 4; i++) {
                int c = tid + i * 256;
                int r = c >> 3, cc = (c & 7) * 8;
                cp16(kbase + (r * KST + cc) * 2, Kp + r * 64 + cc);
            }
            #pragma unroll
            for (int i = 0; i < 4; i++) {
                int c = tid + i * 256;
                int r = c >> 4, cc = (c & 15) * 8;
                cp16(vbase + (r * VST + cc) * 2, Vg + (size_t)r * LL + (kt + 1) * 128 + cc);
            }
            cp_commit();
            cp_wait<1>();
        } else {
            cp_wait<0>();
        }
        __syncthreads();

        const unsigned Kb_ = smb + (QS_SZ + (kt & 1) * BUF_SZ) * 2;
        const unsigned Vb_ = Kb_ + KT_SZ * 2;

        // ---- S = Q @ K^T  (16 n-tiles of 8 keys) ----
        float s[16][4] = {};
        #pragma unroll
        for (int kk = 0; kk < 4; kk++) {
            #pragma unroll
            for (int nt2 = 0; nt2 < 8; nt2++) {
                unsigned r0, r1, r2, r3;
                unsigned addr = Kb_ +
                    (((nt2 * 16 + lrow + ln8) * KST) + kk * 16 + lh8) * 2;
                ldmx4(r0, r1, r2, r3, addr);
                mma16816(s[2 * nt2],     qa[kk], r0, r1);
                mma16816(s[2 * nt2 + 1], qa[kk], r2, r3);
            }
        }

        // ---- online softmax (registers + quad shuffles) ----
        float mr0 = -1e30f, mr1 = -1e30f;
        #pragma unroll
        for (int nt = 0; nt < 16; nt++) {
            mr0 = fmaxf(mr0, fmaxf(s[nt][0], s[nt][1]));
            mr1 = fmaxf(mr1, fmaxf(s[nt][2], s[nt][3]));
        }
        mr0 = fmaxf(mr0, __shfl_xor_sync(0xffffffffu, mr0, 1));
        mr0 = fmaxf(mr0, __shfl_xor_sync(0xffffffffu, mr0, 2));
        mr1 = fmaxf(mr1, __shfl_xor_sync(0xffffffffu, mr1, 1));
        mr1 = fmaxf(mr1, __shfl_xor_sync(0xffffffffu, mr1, 2));
        float mn0 = fmaxf(m0, mr0), mn1 = fmaxf(m1, mr1);
        float al0 = ex2f(m0 - mn0), al1 = ex2f(m1 - mn1);
        m0 = mn0; m1 = mn1;

        unsigned aP[8][4];
        float lr0 = 0.f, lr1 = 0.f;
        #pragma unroll
        for (int nt = 0; nt < 16; nt++) {
            float p0 = ex2f(s[nt][0] - mn0);
            float p1 = ex2f(s[nt][1] - mn0);
            float p2 = ex2f(s[nt][2] - mn1);
            float p3 = ex2f(s[nt][3] - mn1);
            lr0 += p0 + p1; lr1 += p2 + p3;
            int k2 = nt >> 1, off = (nt & 1) * 2;
            aP[k2][off]     = packbf2(p0, p1);
            aP[k2][off + 1] = packbf2(p2, p3);
        }
        lr0 += __shfl_xor_sync(0xffffffffu, lr0, 1);
        lr0 += __shfl_xor_sync(0xffffffffu, lr0, 2);
        lr1 += __shfl_xor_sync(0xffffffffu, lr1, 1);
        lr1 += __shfl_xor_sync(0xffffffffu, lr1, 2);
        l0 = l0 * al0 + lr0;
        l1 = l1 * al1 + lr1;

        #pragma unroll
        for (int nt = 0; nt < 8; nt++) {
            o[nt][0] *= al0; o[nt][1] *= al0;
            o[nt][2] *= al1; o[nt][3] *= al1;
        }

        // ---- O += P @ V  (8 dv n-tiles, 8 key k-tiles) ----
        #pragma unroll
        for (int kt2 = 0; kt2 < 8; kt2++) {
            #pragma unroll
            for (int nt2 = 0; nt2 < 4; nt2++) {
                unsigned r0, r1, r2, r3;
                unsigned addr = Vb_ +
                    (((nt2 * 16 + lrow + ln8) * VST) + kt2 * 16 + lh8) * 2;
                ldmx4(r0, r1, r2, r3, addr);
                mma16816(o[2 * nt2],     aP[kt2], r0, r1);
                mma16816(o[2 * nt2 + 1], aP[kt2], r2, r3);
            }
        }
        __syncthreads();
    }

    // ---- epilogue: normalize, split, store ----
    float inv0 = 1.f / l0, inv1 = 1.f / l1;
    size_t row0 = (size_t)bI * 2048 + qt * 128 + w * 16 + g;
    #pragma unroll
    for (int nt = 0; nt < 8; nt++) {
        int col = h * 64 + nt * 8 + 2 * t;
        float v0 = o[nt][0] * inv0, v1 = o[nt][1] * inv0;
        float v2 = o[nt][2] * inv1, v3 = o[nt][3] * inv1;
        bf16 h0, lo0, h1v, lo1, h2, lo2, h3, lo3;
        split_bf16(v0, h0, lo0); split_bf16(v1, h1v, lo1);
        split_bf16(v2, h2, lo2); split_bf16(v3, h3, lo3);
        size_t o0 = row0 * DM + col;
        size_t o1 = (row0 + 8) * DM + col;
        *(__nv_bfloat162*)(g_Ohi + o0) = __nv_bfloat162(h0, h1v);
        *(__nv_bfloat162*)(g_Olo + o0) = __nv_bfloat162(lo0, lo1);
        *(__nv_bfloat162*)(g_Ohi + o1) = __nv_bfloat162(h2, h3);
        *(__nv_bfloat162*)(g_Olo + o1) = __nv_bfloat162(lo2, lo3);
    }
}

// ---------------- row LayerNorm ----------------------------------------------
template <bool SPLIT>
__global__ __launch_bounds__(256) void ln_kernel(
    const float* __restrict__ y, const float* __restrict__ g,
    const float* __restrict__ bta, float* __restrict__ out,
    bf16* __restrict__ outhi, bf16* __restrict__ outlo)
{
    __shared__ float s1[256], s2[256];
    const int row = blockIdx.x;
    const float* yr = y + (size_t)row * DM;
    float v[4];
    float a = 0.f, q = 0.f;
    #pragma unroll
    for (int i = 0; i < 4; i++) {
        v[i] = yr[threadIdx.x + i * 256];
        a += v[i]; q += v[i] * v[i];
    }
    s1[threadIdx.x] = a; s2[threadIdx.x] = q;
    __syncthreads();
    for (int st = 128; st > 0; st >>= 1) {
        if (threadIdx.x < st) {
            s1[threadIdx.x] += s1[threadIdx.x + st];
            s2[threadIdx.x] += s2[threadIdx.x + st];
        }
        __syncthreads();
    }
    const float mu = s1[0] * (1.f / DM);
    const float var = s2[0] * (1.f / DM) - mu * mu;
    const float rstd = rsqrtf(var + EPSLN);
    #pragma unroll
    for (int i = 0; i < 4; i++) {
        int c = threadIdx.x + i * 256;
        size_t o = (size_t)row * DM + c;
        float ov = (v[i] - mu) * rstd * g[c] + bta[c];
        out[o] = ov;
        if (SPLIT) split_bf16(ov, outhi[o], outlo[o]);
    }
}

// ---------------- launch ------------------------------------------------------
extern "C" void kernel_launch(void* const* d_in, const int* in_sizes, int n_in,
                              void* d_out, int out_size)
{
    const float* x   = (const float*)d_in[0];
    const float* Wq  = (const float*)d_in[1];
    const float* bq  = (const float*)d_in[2];
    const float* Wk  = (const float*)d_in[3];
    const float* bk  = (const float*)d_in[4];
    const float* Wv  = (const float*)d_in[5];
    const float* bv  = (const float*)d_in[6];
    const float* Wo  = (const float*)d_in[7];
    const float* g1  = (const float*)d_in[8];
    const float* be1 = (const float*)d_in[9];
    const float* W1  = (const float*)d_in[10];
    const float* b1f = (const float*)d_in[11];
    const float* W2  = (const float*)d_in[12];
    const float* g2  = (const float*)d_in[13];
    const float* be2 = (const float*)d_in[14];
    float* out = (float*)d_out;

    void *pxh, *pxl, *pWqh, *pWql, *pWoh, *pWol, *pW1h, *pW1l, *pW2h, *pW2l;
    void *pbq, *pOh, *pOl, *py1, *ph1, *ph1h, *ph1l, *pffh, *pffl, *py2;
    cudaGetSymbolAddress(&pxh, g_xhi);   cudaGetSymbolAddress(&pxl, g_xlo);
    cudaGetSymbolAddress(&pWqh, g_Wqkvh); cudaGetSymbolAddress(&pWql, g_Wqkvl);
    cudaGetSymbolAddress(&pWoh, g_Woh);  cudaGetSymbolAddress(&pWol, g_Wol);
    cudaGetSymbolAddress(&pW1h, g_W1h);  cudaGetSymbolAddress(&pW1l, g_W1l);
    cudaGetSymbolAddress(&pW2h, g_W2h);  cudaGetSymbolAddress(&pW2l, g_W2l);
    cudaGetSymbolAddress(&pbq, g_bqkv);
    cudaGetSymbolAddress(&pOh, g_Ohi);   cudaGetSymbolAddress(&pOl, g_Olo);
    cudaGetSymbolAddress(&py1, g_y1);    cudaGetSymbolAddress(&ph1, g_h1);
    cudaGetSymbolAddress(&ph1h, g_h1hi); cudaGetSymbolAddress(&ph1l, g_h1lo);
    cudaGetSymbolAddress(&pffh, g_ffhi); cudaGetSymbolAddress(&pffl, g_fflo);
    cudaGetSymbolAddress(&py2, g_y2);

    cudaFuncSetAttribute(gemm3_kernel<0>, cudaFuncAttributeMaxDynamicSharedMemorySize, GEMM_SMEM);
    cudaFuncSetAttribute(gemm3_kernel<1>, cudaFuncAttributeMaxDynamicSharedMemorySize, GEMM_SMEM);
    cudaFuncSetAttribute(gemm3_kernel<2>, cudaFuncAttributeMaxDynamicSharedMemorySize, GEMM_SMEM);
    cudaFuncSetAttribute(attn_kernel, cudaFuncAttributeMaxDynamicSharedMemorySize, ATTN_SMEM);

    // ---- prep
    xsplit_kernel<<<NROWS, 1024>>>(x);
    qkvw_kernel<<<dim3(2, 32, 48), dim3(32, 8)>>>(Wq, Wk, Wv);
    bqkv_kernel<<<3, 1024>>>(bq, bk, bv);
    tsplit_kernel<<<dim3(32, 32),  dim3(32, 8)>>>(Wo, (bf16*)pWoh, (bf16*)pWol, 1024, 1024);
    tsplit_kernel<<<dim3(128, 32), dim3(32, 8)>>>(W1, (bf16*)pW1h, (bf16*)pW1l, 1024, 4096);
    tsplit_kernel<<<dim3(32, 128), dim3(32, 8)>>>(W2, (bf16*)pW2h, (bf16*)pW2l, 4096, 1024);

    // ---- 1) QKV projection -> bf16 Q(scaled)/K/V^T
    gemm3_kernel<0><<<dim3(24, 32), 256, GEMM_SMEM>>>(
        (const bf16*)pxh, (const bf16*)pxl, (const bf16*)pWqh, (const bf16*)pWql,
        (const float*)pbq, nullptr, nullptr, nullptr, nullptr, 1024, 3072);

    // ---- 2) tensor-core flash attention
    attn_kernel<<<dim3(16, HEADS), 256, ATTN_SMEM>>>();

    // ---- 3) O-proj + residual x -> y1
    gemm3_kernel<1><<<dim3(8, 32), 256, GEMM_SMEM>>>(
        (const bf16*)pOh, (const bf16*)pOl, (const bf16*)pWoh, (const bf16*)pWol,
        nullptr, x, (float*)py1, nullptr, nullptr, 1024, 1024);

    // ---- 4) LayerNorm 1
    ln_kernel<true><<<NROWS, 256>>>((const float*)py1, g1, be1,
                                    (float*)ph1, (bf16*)ph1h, (bf16*)ph1l);

    // ---- 5) FFN up + bias + ReLU
    gemm3_kernel<2><<<dim3(32, 32), 256, GEMM_SMEM>>>(
        (const bf16*)ph1h, (const bf16*)ph1l, (const bf16*)pW1h, (const bf16*)pW1l,
        b1f, nullptr, nullptr, (bf16*)pffh, (bf16*)pffl, 1024, 4096);

    // ---- 6) FFN down + residual h1 -> y2
    gemm3_kernel<1><<<dim3(8, 32), 256, GEMM_SMEM>>>(
        (const bf16*)pffh, (const bf16*)pffl, (const bf16*)pW2h, (const bf16*)pW2l,
        nullptr, (const float*)ph1, (float*)py2, nullptr, nullptr, 4096, 1024);

    // ---- 7) LayerNorm 2 -> output
    ln_kernel<false><<<NROWS, 256>>>((const float*)py2, g2, be2, out, nullptr, nullptr);
}

// round 5
// speedup vs baseline: 3.2180x; 1.1166x over previous
#include <cuda_runtime.h>
#include <cuda_bf16.h>

#define DM    1024
#define HH    16
#define DK    64
#define BB    2
#define LL    2048
#define NROWS (BB*LL)        /* 4096 */
#define DFF   4096
#define EPSLN 1e-5f
#define HEADS (BB*HH)

typedef __nv_bfloat16 bf16;

// scale for Q: 1/sqrt(64) * log2(e) so softmax can use exp2
#define QSCL 0.18033688011112042f

// ---------------- scratch (device globals; no allocations allowed) ----------
__device__ bf16  g_xhi[(size_t)NROWS * DM],  g_xlo[(size_t)NROWS * DM];
__device__ bf16  g_Wqkvh[3072ULL * 1024],    g_Wqkvl[3072ULL * 1024]; // [n=3072][k=1024]
__device__ bf16  g_Woh[1024ULL * 1024],      g_Wol[1024ULL * 1024];   // [n][k]
__device__ bf16  g_W1h[4096ULL * 1024],      g_W1l[4096ULL * 1024];   // [n=4096][k=1024]
__device__ bf16  g_W2h[1024ULL * 4096],      g_W2l[1024ULL * 4096];   // [n=1024][k=4096]
__device__ float g_bqkv[3072];
__device__ bf16  g_Qb[(size_t)HEADS * LL * DK];   // [bh][l][dk], pre-scaled
__device__ bf16  g_Kb[(size_t)HEADS * LL * DK];   // [bh][l][dk]
__device__ bf16  g_Vt[(size_t)HEADS * DK * LL];   // [bh][dk][l]  (transposed)
__device__ bf16  g_Ohi[(size_t)NROWS * DM],  g_Olo[(size_t)NROWS * DM];
__device__ float g_y1[(size_t)NROWS * DM];
__device__ float g_h1[(size_t)NROWS * DM];
__device__ bf16  g_h1hi[(size_t)NROWS * DM], g_h1lo[(size_t)NROWS * DM];
__device__ bf16  g_ffhi[(size_t)NROWS * DFF], g_fflo[(size_t)NROWS * DFF];
__device__ float g_y2[(size_t)NROWS * DM];

__device__ __forceinline__ void split_bf16(float v, bf16& h, bf16& l) {
    h = __float2bfloat16(v);
    l = __float2bfloat16(v - __bfloat162float(h));
}

__device__ __forceinline__ void mma16816(float* d, const unsigned* a,
                                         unsigned b0, unsigned b1) {
    asm volatile(
        "mma.sync.aligned.m16n8k16.row.col.f32.bf16.bf16.f32 "
        "{%0,%1,%2,%3}, {%4,%5,%6,%7}, {%8,%9}, {%0,%1,%2,%3};"
        : "+f"(d[0]), "+f"(d[1]), "+f"(d[2]), "+f"(d[3])
        : "r"(a[0]), "r"(a[1]), "r"(a[2]), "r"(a[3]), "r"(b0), "r"(b1));
}
__device__ __forceinline__ unsigned smem_u32(const void* p) {
    unsigned a;
    asm("{ .reg .u64 t; cvta.to.shared.u64 t, %1; cvt.u32.u64 %0, t; }"
        : "=r"(a) : "l"(p));
    return a;
}
__device__ __forceinline__ float ex2f(float x) {
    float y; asm("ex2.approx.f32 %0, %1;" : "=f"(y) : "f"(x)); return y;
}
__device__ __forceinline__ unsigned packbf2(float lo, float hi) {
    unsigned r; asm("cvt.rn.bf16x2.f32 %0, %1, %2;" : "=r"(r) : "f"(hi), "f"(lo));
    return r;
}
__device__ __forceinline__ void ldmx4(unsigned& r0, unsigned& r1, unsigned& r2,
                                      unsigned& r3, unsigned addr) {
    asm volatile("ldmatrix.sync.aligned.m8n8.x4.shared.b16 {%0,%1,%2,%3}, [%4];"
                 : "=r"(r0), "=r"(r1), "=r"(r2), "=r"(r3) : "r"(addr));
}
__device__ __forceinline__ void cp16(unsigned dst, const void* src) {
    asm volatile("cp.async.cg.shared.global [%0], [%1], 16;" :: "r"(dst), "l"(src));
}
__device__ __forceinline__ void cp_commit() {
    asm volatile("cp.async.commit_group;" ::: "memory");
}
template <int N>
__device__ __forceinline__ void cp_wait() {
    asm volatile("cp.async.wait_group %0;" :: "n"(N) : "memory");
}

// ---------------- prep kernels ----------------------------------------------
__global__ void xsplit_kernel(const float* __restrict__ x) {
    size_t i = (size_t)blockIdx.x * 1024 + threadIdx.x;
    split_bf16(x[i], g_xhi[i], g_xlo[i]);
}
__global__ void bqkv_kernel(const float* __restrict__ bq, const float* __restrict__ bk,
                            const float* __restrict__ bv) {
    int z = blockIdx.x;
    const float* s = (z == 0) ? bq : (z == 1) ? bk : bv;
    g_bqkv[z * 1024 + threadIdx.x] = s[threadIdx.x];
}
__global__ void tsplit_kernel(const float* __restrict__ src, bf16* __restrict__ dh,
                              bf16* __restrict__ dl, int K, int N) {
    __shared__ float t[32][33];
    int kb = blockIdx.y * 32, nb = blockIdx.x * 32;
    int tx = threadIdx.x, ty = threadIdx.y;
    #pragma unroll
    for (int i = 0; i < 32; i += 8)
        t[ty + i][tx] = src[(size_t)(kb + ty + i) * N + nb + tx];
    __syncthreads();
    #pragma unroll
    for (int i = 0; i < 32; i += 8) {
        float v = t[tx][ty + i];
        size_t o = (size_t)(nb + ty + i) * K + kb + tx;
        split_bf16(v, dh[o], dl[o]);
    }
}
__global__ void qkvw_kernel(const float* __restrict__ Wq, const float* __restrict__ Wk,
                            const float* __restrict__ Wv) {
    __shared__ float t[32][33];
    int batch = blockIdx.z, z = batch >> 4, h = batch & 15;
    const float* src = ((z == 0) ? Wq : (z == 1) ? Wk : Wv) + (size_t)h * DM * DK;
    int kb = blockIdx.y * 32, nb = blockIdx.x * 32;
    int tx = threadIdx.x, ty = threadIdx.y;
    #pragma unroll
    for (int i = 0; i < 32; i += 8)
        t[ty + i][tx] = src[(size_t)(kb + ty + i) * DK + nb + tx];
    __syncthreads();
    #pragma unroll
    for (int i = 0; i < 32; i += 8) {
        float v = t[tx][ty + i];
        int ng = z * 1024 + h * 64 + nb + ty + i;
        size_t o = (size_t)ng * DM + kb + tx;
        split_bf16(v, g_Wqkvh[o], g_Wqkvl[o]);
    }
}

// ---------------- mma.sync bf16x3 GEMM (cp.async + ldmatrix, BK=64) ----------
#define GST 72                        /* smem row stride (bf16) */
#define GTILE (128 * GST)             /* one 128x64 tile (padded) */
#define GSTAGE (4 * GTILE)            /* Ah, Al, Bh, Bl */
#define GEMM_SMEM (2 * GSTAGE * 2)    /* bytes: 147456 */

template <int EPI>
__global__ __launch_bounds__(256) void gemm3_kernel(
    const bf16* __restrict__ Ahi, const bf16* __restrict__ Alo,
    const bf16* __restrict__ Bhi, const bf16* __restrict__ Blo,
    const float* __restrict__ bias, const float* __restrict__ res,
    float* __restrict__ outf, bf16* __restrict__ outhi, bf16* __restrict__ outlo,
    int K, int N)
{
    extern __shared__ bf16 smem[];
    const int tid = threadIdx.x;
    const int lane = tid & 31, wid = tid >> 5;
    const int wm = wid & 3, wn = wid >> 2;       // 4 x 2 warp grid
    const int g = lane >> 2, l2 = (lane & 3) * 2;
    const int m0 = blockIdx.y * 128, n0 = blockIdx.x * 128;
    const int nk = K >> 6;
    const unsigned smb = smem_u32(smem);

    // ldmatrix lane addressing
    const int lrow = lane & 7;
    const int arow = lrow + ((lane >> 3) & 1) * 8;   // A: row-in-16
    const int acol = (lane >> 4) << 3;               // A: col offset
    const int brow = lrow + ((lane >> 4) << 3);      // B: row-in-16
    const int bcol = ((lane >> 3) & 1) << 3;         // B: col offset

    // cp.async chunk addressing (per tile: 1024 16B-chunks, 4 per thread)
    const int cr0 = tid >> 3;            // rows advance by 32 per i
    const int ccc = (tid & 7) * 8;

    float d[2][8][4] = {};

    // ---- prefetch stage 0 ----
    {
        unsigned sb = smb;
        #pragma unroll
        for (int i = 0; i < 4; i++) {
            int r = cr0 + i * 32;
            size_t ga = (size_t)(m0 + r) * K + ccc;
            size_t gb = (size_t)(n0 + r) * K + ccc;
            unsigned off = (r * GST + ccc) * 2;
            cp16(sb + off,                  Ahi + ga);
            cp16(sb + GTILE * 2 + off,      Alo + ga);
            cp16(sb + GTILE * 4 + off,      Bhi + gb);
            cp16(sb + GTILE * 6 + off,      Blo + gb);
        }
        cp_commit();
    }

    for (int ks = 0; ks < nk; ks++) {
        if (ks + 1 < nk) {
            const int k0 = (ks + 1) << 6;
            unsigned sb = smb + ((ks + 1) & 1) * (GSTAGE * 2);
            #pragma unroll
            for (int i = 0; i < 4; i++) {
                int r = cr0 + i * 32;
                size_t ga = (size_t)(m0 + r) * K + k0 + ccc;
                size_t gb = (size_t)(n0 + r) * K + k0 + ccc;
                unsigned off = (r * GST + ccc) * 2;
                cp16(sb + off,                  Ahi + ga);
                cp16(sb + GTILE * 2 + off,      Alo + ga);
                cp16(sb + GTILE * 4 + off,      Bhi + gb);
                cp16(sb + GTILE * 6 + off,      Blo + gb);
            }
            cp_commit();
            cp_wait<1>();
        } else {
            cp_wait<0>();
        }
        __syncthreads();

        const unsigned sAh = smb + (ks & 1) * (GSTAGE * 2);
        const unsigned sAl = sAh + GTILE * 2;
        const unsigned sBh = sAh + GTILE * 4;
        const unsigned sBl = sAh + GTILE * 6;

        #pragma unroll
        for (int kk = 0; kk < 4; kk++) {
            unsigned ah[2][4], al[2][4];
            #pragma unroll
            for (int mt = 0; mt < 2; mt++) {
                unsigned aoff = (((wm * 32 + mt * 16 + arow) * GST) + kk * 16 + acol) * 2;
                ldmx4(ah[mt][0], ah[mt][1], ah[mt][2], ah[mt][3], sAh + aoff);
                ldmx4(al[mt][0], al[mt][1], al[mt][2], al[mt][3], sAl + aoff);
            }
            #pragma unroll
            for (int nt2 = 0; nt2 < 4; nt2++) {
                unsigned boff = (((wn * 64 + nt2 * 16 + brow) * GST) + kk * 16 + bcol) * 2;
                unsigned bh0, bh1, bh2, bh3, bl0, bl1, bl2, bl3;
                ldmx4(bh0, bh1, bh2, bh3, sBh + boff);
                ldmx4(bl0, bl1, bl2, bl3, sBl + boff);
                #pragma unroll
                for (int mt = 0; mt < 2; mt++) {
                    mma16816(d[mt][2 * nt2],     ah[mt], bh0, bh1);
                    mma16816(d[mt][2 * nt2],     ah[mt], bl0, bl1);
                    mma16816(d[mt][2 * nt2],     al[mt], bh0, bh1);
                    mma16816(d[mt][2 * nt2 + 1], ah[mt], bh2, bh3);
                    mma16816(d[mt][2 * nt2 + 1], ah[mt], bl2, bl3);
                    mma16816(d[mt][2 * nt2 + 1], al[mt], bh2, bh3);
                }
            }
        }
        __syncthreads();
    }

    // ---- epilogue: fragment rows g, g+8; cols l2, l2+1 of each 16x8 tile ----
    #pragma unroll
    for (int mt = 0; mt < 2; mt++) {
        #pragma unroll
        for (int nt = 0; nt < 8; nt++) {
            int rbase = m0 + wm * 32 + mt * 16 + g;
            int cc = n0 + wn * 64 + nt * 8 + l2;
            #pragma unroll
            for (int rr = 0; rr < 2; rr++) {
                int rg = rbase + rr * 8;
                float v0 = d[mt][nt][rr * 2 + 0];
                float v1 = d[mt][nt][rr * 2 + 1];
                if (EPI == 0) {
                    // QKV epilogue: bf16 Q (scaled), K, V^T
                    float2 bv = *(const float2*)(bias + cc);
                    float w0 = v0 + bv.x, w1 = v1 + bv.y;
                    int z = cc >> 10, h = (cc >> 6) & 15, dk = cc & 63;
                    int bb_ = rg >> 11, lpos = rg & 2047;
                    size_t headbase = (size_t)(bb_ * 16 + h);
                    if (z == 0) {
                        w0 *= QSCL; w1 *= QSCL;
                        *(__nv_bfloat162*)(g_Qb + (headbase * 2048 + lpos) * 64 + dk) =
                            __nv_bfloat162(__float2bfloat16(w0), __float2bfloat16(w1));
                    } else if (z == 1) {
                        *(__nv_bfloat162*)(g_Kb + (headbase * 2048 + lpos) * 64 + dk) =
                            __nv_bfloat162(__float2bfloat16(w0), __float2bfloat16(w1));
                    } else {
                        size_t vb = (headbase * 64 + dk) * 2048 + lpos;
                        g_Vt[vb] = __float2bfloat16(w0);
                        g_Vt[vb + 2048] = __float2bfloat16(w1);
                    }
                } else if (EPI == 1) {
                    size_t o = (size_t)rg * N + cc;
                    float2 rv = *(const float2*)(res + o);
                    *(float2*)(outf + o) = make_float2(v0 + rv.x, v1 + rv.y);
                } else {
                    size_t o = (size_t)rg * N + cc;
                    float2 bv = *(const float2*)(bias + cc);
                    float w0 = fmaxf(v0 + bv.x, 0.f);
                    float w1 = fmaxf(v1 + bv.y, 0.f);
                    bf16 h0, l0, h1b, l1;
                    split_bf16(w0, h0, l0);
                    split_bf16(w1, h1b, l1);
                    *(__nv_bfloat162*)(outhi + o) = __nv_bfloat162(h0, h1b);
                    *(__nv_bfloat162*)(outlo + o) = __nv_bfloat162(l0, l1);
                }
            }
        }
    }
}

// ---------------- bf16 tensor-core flash attention ---------------------------
#define KST 72            /* K/Q smem row stride (bf16) */
#define VST 136           /* Vt smem row stride (bf16) */
#define QS_SZ   (128 * KST)
#define KT_SZ   (128 * KST)
#define VT_SZ   (64 * VST)
#define BUF_SZ  (KT_SZ + VT_SZ)
#define ATTN_SMEM ((QS_SZ + 2 * BUF_SZ) * 2)   /* bytes */

__global__ __launch_bounds__(256, 1) void attn_kernel()
{
    extern __shared__ bf16 sm[];
    bf16* Qs = sm;
    const int tid = threadIdx.x, lane = tid & 31, w = tid >> 5;
    const int g = lane >> 2, t = lane & 3;
    const int qt = blockIdx.x, bh = blockIdx.y;
    const int bI = bh >> 4, h = bh & 15;

    const bf16* Qg = g_Qb + ((size_t)bh * LL + qt * 128) * 64;
    const bf16* Kg = g_Kb + (size_t)bh * LL * 64;
    const bf16* Vg = g_Vt + (size_t)bh * 64 * LL;
    const unsigned smb = smem_u32(sm);

    // stage Q (plain loads)
    #pragma unroll
    for (int i = 0; i < 4; i++) {
        int c = tid + i * 256;
        int r = c >> 3, cc = (c & 7) * 8;
        *(uint4*)(Qs + r * KST + cc) = *(const uint4*)(Qg + r * 64 + cc);
    }

    // prefetch tile 0 via cp.async
    {
        unsigned kbase = smb + QS_SZ * 2;
        unsigned vbase = kbase + KT_SZ * 2;
        #pragma unroll
        for (int i = 0; i < 4; i++) {
            int c = tid + i * 256;
            int r = c >> 3, cc = (c & 7) * 8;
            cp16(kbase + (r * KST + cc) * 2, Kg + r * 64 + cc);
        }
        #pragma unroll
        for (int i = 0; i < 4; i++) {
            int c = tid + i * 256;
            int r = c >> 4, cc = (c & 15) * 8;
            cp16(vbase + (r * VST + cc) * 2, Vg + (size_t)r * LL + cc);
        }
        cp_commit();
    }
    __syncthreads();

    // Q fragments (16x64 per warp)
    unsigned qa[4][4];
    {
        const int qrow = w * 16 + g;
        #pragma unroll
        for (int kk = 0; kk < 4; kk++) {
            qa[kk][0] = *(const unsigned*)(Qs + qrow * KST + kk * 16 + 2 * t);
            qa[kk][1] = *(const unsigned*)(Qs + (qrow + 8) * KST + kk * 16 + 2 * t);
            qa[kk][2] = *(const unsigned*)(Qs + qrow * KST + kk * 16 + 8 + 2 * t);
            qa[kk][3] = *(const unsigned*)(Qs + (qrow + 8) * KST + kk * 16 + 8 + 2 * t);
        }
    }

    float m0 = -1e30f, m1 = -1e30f, l0 = 0.f, l1 = 0.f;
    float o[8][4] = {};

    const int lrow = lane & 7;
    const int lh8  = ((lane >> 3) & 1) << 3;
    const int ln8  = (lane >> 4) << 3;

    for (int kt = 0; kt < 16; kt++) {
        if (kt + 1 < 16) {
            int nb = (kt + 1) & 1;
            unsigned kbase = smb + (QS_SZ + nb * BUF_SZ) * 2;
            unsigned vbase = kbase + KT_SZ * 2;
            const bf16* Kp = Kg + (size_t)(kt + 1) * 128 * 64;
            #pragma unroll
            for (int i = 0; i < 4; i++) {
                int c = tid + i * 256;
                int r = c >> 3, cc = (c & 7) * 8;
                cp16(kbase + (r * KST + cc) * 2, Kp + r * 64 + cc);
            }
            #pragma unroll
            for (int i = 0; i < 4; i++) {
                int c = tid + i * 256;
                int r = c >> 4, cc = (c & 15) * 8;
                cp16(vbase + (r * VST + cc) * 2, Vg + (size_t)r * LL + (kt + 1) * 128 + cc);
            }
            cp_commit();
            cp_wait<1>();
        } else {
            cp_wait<0>();
        }
        __syncthreads();

        const unsigned Kb_ = smb + (QS_SZ + (kt & 1) * BUF_SZ) * 2;
        const unsigned Vb_ = Kb_ + KT_SZ * 2;

        // ---- S = Q @ K^T ----
        float s[16][4] = {};
        #pragma unroll
        for (int kk = 0; kk < 4; kk++) {
            #pragma unroll
            for (int nt2 = 0; nt2 < 8; nt2++) {
                unsigned r0, r1, r2, r3;
                unsigned addr = Kb_ +
                    (((nt2 * 16 + lrow + ln8) * KST) + kk * 16 + lh8) * 2;
                ldmx4(r0, r1, r2, r3, addr);
                mma16816(s[2 * nt2],     qa[kk], r0, r1);
                mma16816(s[2 * nt2 + 1], qa[kk], r2, r3);
            }
        }

        // ---- online softmax ----
        float mr0 = -1e30f, mr1 = -1e30f;
        #pragma unroll
        for (int nt = 0; nt < 16; nt++) {
            mr0 = fmaxf(mr0, fmaxf(s[nt][0], s[nt][1]));
            mr1 = fmaxf(mr1, fmaxf(s[nt][2], s[nt][3]));
        }
        mr0 = fmaxf(mr0, __shfl_xor_sync(0xffffffffu, mr0, 1));
        mr0 = fmaxf(mr0, __shfl_xor_sync(0xffffffffu, mr0, 2));
        mr1 = fmaxf(mr1, __shfl_xor_sync(0xffffffffu, mr1, 1));
        mr1 = fmaxf(mr1, __shfl_xor_sync(0xffffffffu, mr1, 2));
        float mn0 = fmaxf(m0, mr0), mn1 = fmaxf(m1, mr1);
        float al0 = ex2f(m0 - mn0), al1 = ex2f(m1 - mn1);
        m0 = mn0; m1 = mn1;

        unsigned aP[8][4];
        float lr0 = 0.f, lr1 = 0.f;
        #pragma unroll
        for (int nt = 0; nt < 16; nt++) {
            float p0 = ex2f(s[nt][0] - mn0);
            float p1 = ex2f(s[nt][1] - mn0);
            float p2 = ex2f(s[nt][2] - mn1);
            float p3 = ex2f(s[nt][3] - mn1);
            lr0 += p0 + p1; lr1 += p2 + p3;
            int k2 = nt >> 1, off = (nt & 1) * 2;
            aP[k2][off]     = packbf2(p0, p1);
            aP[k2][off + 1] = packbf2(p2, p3);
        }
        lr0 += __shfl_xor_sync(0xffffffffu, lr0, 1);
        lr0 += __shfl_xor_sync(0xffffffffu, lr0, 2);
        lr1 += __shfl_xor_sync(0xffffffffu, lr1, 1);
        lr1 += __shfl_xor_sync(0xffffffffu, lr1, 2);
        l0 = l0 * al0 + lr0;
        l1 = l1 * al1 + lr1;

        #pragma unroll
        for (int nt = 0; nt < 8; nt++) {
            o[nt][0] *= al0; o[nt][1] *= al0;
            o[nt][2] *= al1; o[nt][3] *= al1;
        }

        // ---- O += P @ V ----
        #pragma unroll
        for (int kt2 = 0; kt2 < 8; kt2++) {
            #pragma unroll
            for (int nt2 = 0; nt2 < 4; nt2++) {
                unsigned r0, r1, r2, r3;
                unsigned addr = Vb_ +
                    (((nt2 * 16 + lrow + ln8) * VST) + kt2 * 16 + lh8) * 2;
                ldmx4(r0, r1, r2, r3, addr);
                mma16816(o[2 * nt2],     aP[kt2], r0, r1);
                mma16816(o[2 * nt2 + 1], aP[kt2], r2, r3);
            }
        }
        __syncthreads();
    }

    // ---- epilogue ----
    float inv0 = 1.f / l0, inv1 = 1.f / l1;
    size_t row0 = (size_t)bI * 2048 + qt * 128 + w * 16 + g;
    #pragma unroll
    for (int nt = 0; nt < 8; nt++) {
        int col = h * 64 + nt * 8 + 2 * t;
        float v0 = o[nt][0] * inv0, v1 = o[nt][1] * inv0;
        float v2 = o[nt][2] * inv1, v3 = o[nt][3] * inv1;
        bf16 h0, lo0, h1v, lo1, h2, lo2, h3, lo3;
        split_bf16(v0, h0, lo0); split_bf16(v1, h1v, lo1);
        split_bf16(v2, h2, lo2); split_bf16(v3, h3, lo3);
        size_t o0 = row0 * DM + col;
        size_t o1 = (row0 + 8) * DM + col;
        *(__nv_bfloat162*)(g_Ohi + o0) = __nv_bfloat162(h0, h1v);
        *(__nv_bfloat162*)(g_Olo + o0) = __nv_bfloat162(lo0, lo1);
        *(__nv_bfloat162*)(g_Ohi + o1) = __nv_bfloat162(h2, h3);
        *(__nv_bfloat162*)(g_Olo + o1) = __nv_bfloat162(lo2, lo3);
    }
}

// ---------------- row LayerNorm ----------------------------------------------
template <bool SPLIT>
__global__ __launch_bounds__(256) void ln_kernel(
    const float* __restrict__ y, const float* __restrict__ g,
    const float* __restrict__ bta, float* __restrict__ out,
    bf16* __restrict__ outhi, bf16* __restrict__ outlo)
{
    __shared__ float s1[256], s2[256];
    const int row = blockIdx.x;
    const float* yr = y + (size_t)row * DM;
    float v[4];
    float a = 0.f, q = 0.f;
    #pragma unroll
    for (int i = 0; i < 4; i++) {
        v[i] = yr[threadIdx.x + i * 256];
        a += v[i]; q += v[i] * v[i];
    }
    s1[threadIdx.x] = a; s2[threadIdx.x] = q;
    __syncthreads();
    for (int st = 128; st > 0; st >>= 1) {
        if (threadIdx.x < st) {
            s1[threadIdx.x] += s1[threadIdx.x + st];
            s2[threadIdx.x] += s2[threadIdx.x + st];
        }
        __syncthreads();
    }
    const float mu = s1[0] * (1.f / DM);
    const float var = s2[0] * (1.f / DM) - mu * mu;
    const float rstd = rsqrtf(var + EPSLN);
    #pragma unroll
    for (int i = 0; i < 4; i++) {
        int c = threadIdx.x + i * 256;
        size_t o = (size_t)row * DM + c;
        float ov = (v[i] - mu) * rstd * g[c] + bta[c];
        out[o] = ov;
        if (SPLIT) split_bf16(ov, outhi[o], outlo[o]);
    }
}

// ---------------- launch ------------------------------------------------------
extern "C" void kernel_launch(void* const* d_in, const int* in_sizes, int n_in,
                              void* d_out, int out_size)
{
    const float* x   = (const float*)d_in[0];
    const float* Wq  = (const float*)d_in[1];
    const float* bq  = (const float*)d_in[2];
    const float* Wk  = (const float*)d_in[3];
    const float* bk  = (const float*)d_in[4];
    const float* Wv  = (const float*)d_in[5];
    const float* bv  = (const float*)d_in[6];
    const float* Wo  = (const float*)d_in[7];
    const float* g1  = (const float*)d_in[8];
    const float* be1 = (const float*)d_in[9];
    const float* W1  = (const float*)d_in[10];
    const float* b1f = (const float*)d_in[11];
    const float* W2  = (const float*)d_in[12];
    const float* g2  = (const float*)d_in[13];
    const float* be2 = (const float*)d_in[14];
    float* out = (float*)d_out;

    void *pxh, *pxl, *pWqh, *pWql, *pWoh, *pWol, *pW1h, *pW1l, *pW2h, *pW2l;
    void *pbq, *pOh, *pOl, *py1, *ph1, *ph1h, *ph1l, *pffh, *pffl, *py2;
    cudaGetSymbolAddress(&pxh, g_xhi);   cudaGetSymbolAddress(&pxl, g_xlo);
    cudaGetSymbolAddress(&pWqh, g_Wqkvh); cudaGetSymbolAddress(&pWql, g_Wqkvl);
    cudaGetSymbolAddress(&pWoh, g_Woh);  cudaGetSymbolAddress(&pWol, g_Wol);
    cudaGetSymbolAddress(&pW1h, g_W1h);  cudaGetSymbolAddress(&pW1l, g_W1l);
    cudaGetSymbolAddress(&pW2h, g_W2h);  cudaGetSymbolAddress(&pW2l, g_W2l);
    cudaGetSymbolAddress(&pbq, g_bqkv);
    cudaGetSymbolAddress(&pOh, g_Ohi);   cudaGetSymbolAddress(&pOl, g_Olo);
    cudaGetSymbolAddress(&py1, g_y1);    cudaGetSymbolAddress(&ph1, g_h1);
    cudaGetSymbolAddress(&ph1h, g_h1hi); cudaGetSymbolAddress(&ph1l, g_h1lo);
    cudaGetSymbolAddress(&pffh, g_ffhi); cudaGetSymbolAddress(&pffl, g_fflo);
    cudaGetSymbolAddress(&py2, g_y2);

    cudaFuncSetAttribute(gemm3_kernel<0>, cudaFuncAttributeMaxDynamicSharedMemorySize, GEMM_SMEM);
    cudaFuncSetAttribute(gemm3_kernel<1>, cudaFuncAttributeMaxDynamicSharedMemorySize, GEMM_SMEM);
    cudaFuncSetAttribute(gemm3_kernel<2>, cudaFuncAttributeMaxDynamicSharedMemorySize, GEMM_SMEM);
    cudaFuncSetAttribute(attn_kernel, cudaFuncAttributeMaxDynamicSharedMemorySize, ATTN_SMEM);

    // ---- prep
    xsplit_kernel<<<NROWS, 1024>>>(x);
    qkvw_kernel<<<dim3(2, 32, 48), dim3(32, 8)>>>(Wq, Wk, Wv);
    bqkv_kernel<<<3, 1024>>>(bq, bk, bv);
    tsplit_kernel<<<dim3(32, 32),  dim3(32, 8)>>>(Wo, (bf16*)pWoh, (bf16*)pWol, 1024, 1024);
    tsplit_kernel<<<dim3(128, 32), dim3(32, 8)>>>(W1, (bf16*)pW1h, (bf16*)pW1l, 1024, 4096);
    tsplit_kernel<<<dim3(32, 128), dim3(32, 8)>>>(W2, (bf16*)pW2h, (bf16*)pW2l, 4096, 1024);

    // ---- 1) QKV projection -> bf16 Q(scaled)/K/V^T
    gemm3_kernel<0><<<dim3(24, 32), 256, GEMM_SMEM>>>(
        (const bf16*)pxh, (const bf16*)pxl, (const bf16*)pWqh, (const bf16*)pWql,
        (const float*)pbq, nullptr, nullptr, nullptr, nullptr, 1024, 3072);

    // ---- 2) tensor-core flash attention
    attn_kernel<<<dim3(16, HEADS), 256, ATTN_SMEM>>>();

    // ---- 3) O-proj + residual x -> y1
    gemm3_kernel<1><<<dim3(8, 32), 256, GEMM_SMEM>>>(
        (const bf16*)pOh, (const bf16*)pOl, (const bf16*)pWoh, (const bf16*)pWol,
        nullptr, x, (float*)py1, nullptr, nullptr, 1024, 1024);

    // ---- 4) LayerNorm 1
    ln_kernel<true><<<NROWS, 256>>>((const float*)py1, g1, be1,
                                    (float*)ph1, (bf16*)ph1h, (bf16*)ph1l);

    // ---- 5) FFN up + bias + ReLU
    gemm3_kernel<2><<<dim3(32, 32), 256, GEMM_SMEM>>>(
        (const bf16*)ph1h, (const bf16*)ph1l, (const bf16*)pW1h, (const bf16*)pW1l,
        b1f, nullptr, nullptr, (bf16*)pffh, (bf16*)pffl, 1024, 4096);

    // ---- 6) FFN down + residual h1 -> y2
    gemm3_kernel<1><<<dim3(8, 32), 256, GEMM_SMEM>>>(
        (const bf16*)pffh, (const bf16*)pffl, (const bf16*)pW2h, (const bf16*)pW2l,
        nullptr, (const float*)ph1, (float*)py2, nullptr, nullptr, 4096, 1024);

    // ---- 7) LayerNorm 2 -> output
    ln_kernel<false><<<NROWS, 256>>>((const float*)py2, g2, be2, out, nullptr, nullptr);
}

// round 6
// speedup vs baseline: 6.8224x; 2.1201x over previous
#include <cuda_runtime.h>
#include <cuda_fp16.h>

#define DM    1024
#define HH    16
#define DK    64
#define BB    2
#define LL    2048
#define NROWS (BB*LL)        /* 4096 */
#define DFF   4096
#define EPSLN 1e-5f
#define HEADS (BB*HH)

typedef __half fp16;

// scale for Q: 1/sqrt(64) * log2(e) so softmax can use exp2
#define QSCL 0.18033688011112042f

// ---------------- scratch (device globals; no allocations allowed) ----------
__device__ fp16  g_x16[(size_t)NROWS * DM];
__device__ fp16  g_Wqkv[3072ULL * 1024];      // [n=3072][k=1024]
__device__ fp16  g_Wo16[1024ULL * 1024];      // [n][k]
__device__ fp16  g_W116[4096ULL * 1024];      // [n=4096][k=1024]
__device__ fp16  g_W216[1024ULL * 4096];      // [n=1024][k=4096]
__device__ float g_bqkv[3072];
__device__ fp16  g_Qb[(size_t)HEADS * LL * DK];   // [bh][l][dk], pre-scaled
__device__ fp16  g_Kb[(size_t)HEADS * LL * DK];   // [bh][l][dk]
__device__ fp16  g_Vt[(size_t)HEADS * DK * LL];   // [bh][dk][l]  (transposed)
__device__ fp16  g_O16[(size_t)NROWS * DM];
__device__ float g_y1[(size_t)NROWS * DM];
__device__ float g_h1[(size_t)NROWS * DM];
__device__ fp16  g_h116[(size_t)NROWS * DM];
__device__ fp16  g_ff16[(size_t)NROWS * DFF];
__device__ float g_y2[(size_t)NROWS * DM];

__device__ __forceinline__ void mma16816(float* d, const unsigned* a,
                                         unsigned b0, unsigned b1) {
    asm volatile(
        "mma.sync.aligned.m16n8k16.row.col.f32.f16.f16.f32 "
        "{%0,%1,%2,%3}, {%4,%5,%6,%7}, {%8,%9}, {%0,%1,%2,%3};"
        : "+f"(d[0]), "+f"(d[1]), "+f"(d[2]), "+f"(d[3])
        : "r"(a[0]), "r"(a[1]), "r"(a[2]), "r"(a[3]), "r"(b0), "r"(b1));
}
__device__ __forceinline__ unsigned smem_u32(const void* p) {
    unsigned a;
    asm("{ .reg .u64 t; cvta.to.shared.u64 t, %1; cvt.u32.u64 %0, t; }"
        : "=r"(a) : "l"(p));
    return a;
}
__device__ __forceinline__ float ex2f(float x) {
    float y; asm("ex2.approx.f32 %0, %1;" : "=f"(y) : "f"(x)); return y;
}
__device__ __forceinline__ unsigned packh2(float lo, float hi) {
    unsigned r; asm("cvt.rn.f16x2.f32 %0, %1, %2;" : "=r"(r) : "f"(hi), "f"(lo));
    return r;
}
__device__ __forceinline__ void ldmx4(unsigned& r0, unsigned& r1, unsigned& r2,
                                      unsigned& r3, unsigned addr) {
    asm volatile("ldmatrix.sync.aligned.m8n8.x4.shared.b16 {%0,%1,%2,%3}, [%4];"
                 : "=r"(r0), "=r"(r1), "=r"(r2), "=r"(r3) : "r"(addr));
}
__device__ __forceinline__ void cp16(unsigned dst, const void* src) {
    asm volatile("cp.async.cg.shared.global [%0], [%1], 16;" :: "r"(dst), "l"(src));
}
__device__ __forceinline__ void cp_commit() {
    asm volatile("cp.async.commit_group;" ::: "memory");
}
template <int N>
__device__ __forceinline__ void cp_wait() {
    asm volatile("cp.async.wait_group %0;" :: "n"(N) : "memory");
}

// ---------------- prep kernels ----------------------------------------------
__global__ void xhalf_kernel(const float* __restrict__ x) {
    size_t i = (size_t)blockIdx.x * 1024 + threadIdx.x;
    g_x16[i] = __float2half_rn(x[i]);
}
__global__ void bqkv_kernel(const float* __restrict__ bq, const float* __restrict__ bk,
                            const float* __restrict__ bv) {
    int z = blockIdx.x;
    const float* s = (z == 0) ? bq : (z == 1) ? bk : bv;
    g_bqkv[z * 1024 + threadIdx.x] = s[threadIdx.x];
}
// transpose + fp16 convert: src[K][N] -> dst[N][K]
__global__ void thalf_kernel(const float* __restrict__ src, fp16* __restrict__ d,
                             int K, int N) {
    __shared__ float t[32][33];
    int kb = blockIdx.y * 32, nb = blockIdx.x * 32;
    int tx = threadIdx.x, ty = threadIdx.y;
    #pragma unroll
    for (int i = 0; i < 32; i += 8)
        t[ty + i][tx] = src[(size_t)(kb + ty + i) * N + nb + tx];
    __syncthreads();
    #pragma unroll
    for (int i = 0; i < 32; i += 8)
        d[(size_t)(nb + ty + i) * K + kb + tx] = __float2half_rn(t[tx][ty + i]);
}
// QKV weights: W_z[h][1024][64] -> g_Wqkv[n = z*1024 + h*64 + dk][k]
__global__ void qkvw_kernel(const float* __restrict__ Wq, const float* __restrict__ Wk,
                            const float* __restrict__ Wv) {
    __shared__ float t[32][33];
    int batch = blockIdx.z, z = batch >> 4, h = batch & 15;
    const float* src = ((z == 0) ? Wq : (z == 1) ? Wk : Wv) + (size_t)h * DM * DK;
    int kb = blockIdx.y * 32, nb = blockIdx.x * 32;
    int tx = threadIdx.x, ty = threadIdx.y;
    #pragma unroll
    for (int i = 0; i < 32; i += 8)
        t[ty + i][tx] = src[(size_t)(kb + ty + i) * DK + nb + tx];
    __syncthreads();
    #pragma unroll
    for (int i = 0; i < 32; i += 8) {
        int ng = z * 1024 + h * 64 + nb + ty + i;
        g_Wqkv[(size_t)ng * DM + kb + tx] = __float2half_rn(t[tx][ty + i]);
    }
}

// ---------------- fp16 mma.sync GEMM (cp.async + ldmatrix, BK=64) ------------
#define GST 72                        /* smem row stride (fp16) */
#define GTILE (128 * GST)             /* one 128x64 tile (padded) */
#define GSTAGE (2 * GTILE)            /* A, B */
#define GEMM_SMEM (2 * GSTAGE * 2)    /* bytes: 73728 */

template <int EPI>
__global__ __launch_bounds__(256, 2) void gemm1_kernel(
    const fp16* __restrict__ A, const fp16* __restrict__ B,
    const float* __restrict__ bias, const float* __restrict__ res,
    float* __restrict__ outf, fp16* __restrict__ outh,
    int K, int N)
{
    extern __shared__ fp16 smem[];
    const int tid = threadIdx.x;
    const int lane = tid & 31, wid = tid >> 5;
    const int wm = wid & 3, wn = wid >> 2;       // 4 x 2 warp grid
    const int g = lane >> 2, l2 = (lane & 3) * 2;
    const int m0 = blockIdx.y * 128, n0 = blockIdx.x * 128;
    const int nk = K >> 6;
    const unsigned smb = smem_u32(smem);

    // ldmatrix lane addressing
    const int lrow = lane & 7;
    const int arow = lrow + ((lane >> 3) & 1) * 8;   // A: row-in-16
    const int acol = (lane >> 4) << 3;               // A: col offset
    const int brow = lrow + ((lane >> 4) << 3);      // B: row-in-16
    const int bcol = ((lane >> 3) & 1) << 3;         // B: col offset

    // cp.async chunk addressing
    const int cr0 = tid >> 3;            // rows advance by 32 per i
    const int ccc = (tid & 7) * 8;

    float d[2][8][4] = {};

    // ---- prefetch stage 0 ----
    {
        unsigned sb = smb;
        #pragma unroll
        for (int i = 0; i < 4; i++) {
            int r = cr0 + i * 32;
            unsigned off = (r * GST + ccc) * 2;
            cp16(sb + off,             A + (size_t)(m0 + r) * K + ccc);
            cp16(sb + GTILE * 2 + off, B + (size_t)(n0 + r) * K + ccc);
        }
        cp_commit();
    }

    for (int ks = 0; ks < nk; ks++) {
        if (ks + 1 < nk) {
            const int k0 = (ks + 1) << 6;
            unsigned sb = smb + ((ks + 1) & 1) * (GSTAGE * 2);
            #pragma unroll
            for (int i = 0; i < 4; i++) {
                int r = cr0 + i * 32;
                unsigned off = (r * GST + ccc) * 2;
                cp16(sb + off,             A + (size_t)(m0 + r) * K + k0 + ccc);
                cp16(sb + GTILE * 2 + off, B + (size_t)(n0 + r) * K + k0 + ccc);
            }
            cp_commit();
            cp_wait<1>();
        } else {
            cp_wait<0>();
        }
        __syncthreads();

        const unsigned sA = smb + (ks & 1) * (GSTAGE * 2);
        const unsigned sB = sA + GTILE * 2;

        #pragma unroll
        for (int kk = 0; kk < 4; kk++) {
            unsigned a[2][4];
            #pragma unroll
            for (int mt = 0; mt < 2; mt++) {
                unsigned aoff = (((wm * 32 + mt * 16 + arow) * GST) + kk * 16 + acol) * 2;
                ldmx4(a[mt][0], a[mt][1], a[mt][2], a[mt][3], sA + aoff);
            }
            #pragma unroll
            for (int nt2 = 0; nt2 < 4; nt2++) {
                unsigned boff = (((wn * 64 + nt2 * 16 + brow) * GST) + kk * 16 + bcol) * 2;
                unsigned b0, b1, b2, b3;
                ldmx4(b0, b1, b2, b3, sB + boff);
                #pragma unroll
                for (int mt = 0; mt < 2; mt++) {
                    mma16816(d[mt][2 * nt2],     a[mt], b0, b1);
                    mma16816(d[mt][2 * nt2 + 1], a[mt], b2, b3);
                }
            }
        }
        __syncthreads();
    }

    // ---- epilogue: fragment rows g, g+8; cols l2, l2+1 of each 16x8 tile ----
    #pragma unroll
    for (int mt = 0; mt < 2; mt++) {
        #pragma unroll
        for (int nt = 0; nt < 8; nt++) {
            int rbase = m0 + wm * 32 + mt * 16 + g;
            int cc = n0 + wn * 64 + nt * 8 + l2;
            #pragma unroll
            for (int rr = 0; rr < 2; rr++) {
                int rg = rbase + rr * 8;
                float v0 = d[mt][nt][rr * 2 + 0];
                float v1 = d[mt][nt][rr * 2 + 1];
                if (EPI == 0) {
                    // QKV epilogue: fp16 Q (scaled), K, V^T
                    float2 bv = *(const float2*)(bias + cc);
                    float w0 = v0 + bv.x, w1 = v1 + bv.y;
                    int z = cc >> 10, h = (cc >> 6) & 15, dk = cc & 63;
                    int bb_ = rg >> 11, lpos = rg & 2047;
                    size_t headbase = (size_t)(bb_ * 16 + h);
                    if (z == 0) {
                        w0 *= QSCL; w1 *= QSCL;
                        *(__half2*)(g_Qb + (headbase * 2048 + lpos) * 64 + dk) =
                            __halves2half2(__float2half_rn(w0), __float2half_rn(w1));
                    } else if (z == 1) {
                        *(__half2*)(g_Kb + (headbase * 2048 + lpos) * 64 + dk) =
                            __halves2half2(__float2half_rn(w0), __float2half_rn(w1));
                    } else {
                        size_t vb = (headbase * 64 + dk) * 2048 + lpos;
                        g_Vt[vb] = __float2half_rn(w0);
                        g_Vt[vb + 2048] = __float2half_rn(w1);
                    }
                } else if (EPI == 1) {
                    size_t o = (size_t)rg * N + cc;
                    float2 rv = *(const float2*)(res + o);
                    *(float2*)(outf + o) = make_float2(v0 + rv.x, v1 + rv.y);
                } else {
                    size_t o = (size_t)rg * N + cc;
                    float2 bv = *(const float2*)(bias + cc);
                    float w0 = fmaxf(v0 + bv.x, 0.f);
                    float w1 = fmaxf(v1 + bv.y, 0.f);
                    *(__half2*)(outh + o) =
                        __halves2half2(__float2half_rn(w0), __float2half_rn(w1));
                }
            }
        }
    }
}

// ---------------- fp16 tensor-core flash attention ---------------------------
#define KST 72            /* K/Q smem row stride (fp16) */
#define VST 136           /* Vt smem row stride (fp16) */
#define QS_SZ   (128 * KST)
#define KT_SZ   (128 * KST)
#define VT_SZ   (64 * VST)
#define BUF_SZ  (KT_SZ + VT_SZ)
#define ATTN_SMEM ((QS_SZ + 2 * BUF_SZ) * 2)   /* bytes */

__global__ __launch_bounds__(256, 1) void attn_kernel()
{
    extern __shared__ fp16 sm[];
    fp16* Qs = sm;
    const int tid = threadIdx.x, lane = tid & 31, w = tid >> 5;
    const int g = lane >> 2, t = lane & 3;
    const int qt = blockIdx.x, bh = blockIdx.y;
    const int bI = bh >> 4, h = bh & 15;

    const fp16* Qg = g_Qb + ((size_t)bh * LL + qt * 128) * 64;
    const fp16* Kg = g_Kb + (size_t)bh * LL * 64;
    const fp16* Vg = g_Vt + (size_t)bh * 64 * LL;
    const unsigned smb = smem_u32(sm);

    // stage Q (plain loads)
    #pragma unroll
    for (int i = 0; i < 4; i++) {
        int c = tid + i * 256;
        int r = c >> 3, cc = (c & 7) * 8;
        *(uint4*)(Qs + r * KST + cc) = *(const uint4*)(Qg + r * 64 + cc);
    }

    // prefetch tile 0 via cp.async
    {
        unsigned kbase = smb + QS_SZ * 2;
        unsigned vbase = kbase + KT_SZ * 2;
        #pragma unroll
        for (int i = 0; i < 4; i++) {
            int c = tid + i * 256;
            int r = c >> 3, cc = (c & 7) * 8;
            cp16(kbase + (r * KST + cc) * 2, Kg + r * 64 + cc);
        }
        #pragma unroll
        for (int i = 0; i < 4; i++) {
            int c = tid + i * 256;
            int r = c >> 4, cc = (c & 15) * 8;
            cp16(vbase + (r * VST + cc) * 2, Vg + (size_t)r * LL + cc);
        }
        cp_commit();
    }
    __syncthreads();

    // Q fragments (16x64 per warp)
    unsigned qa[4][4];
    {
        const int qrow = w * 16 + g;
        #pragma unroll
        for (int kk = 0; kk < 4; kk++) {
            qa[kk][0] = *(const unsigned*)(Qs + qrow * KST + kk * 16 + 2 * t);
            qa[kk][1] = *(const unsigned*)(Qs + (qrow + 8) * KST + kk * 16 + 2 * t);
            qa[kk][2] = *(const unsigned*)(Qs + qrow * KST + kk * 16 + 8 + 2 * t);
            qa[kk][3] = *(const unsigned*)(Qs + (qrow + 8) * KST + kk * 16 + 8 + 2 * t);
        }
    }

    float m0 = -1e30f, m1 = -1e30f, l0 = 0.f, l1 = 0.f;
    float o[8][4] = {};

    const int lrow = lane & 7;
    const int lh8  = ((lane >> 3) & 1) << 3;
    const int ln8  = (lane >> 4) << 3;

    for (int kt = 0; kt < 16; kt++) {
        if (kt + 1 < 16) {
            int nb = (kt + 1) & 1;
            unsigned kbase = smb + (QS_SZ + nb * BUF_SZ) * 2;
            unsigned vbase = kbase + KT_SZ * 2;
            const fp16* Kp = Kg + (size_t)(kt + 1) * 128 * 64;
            #pragma unroll
            for (int i = 0; i < 4; i++) {
                int c = tid + i * 256;
                int r = c >> 3, cc = (c & 7) * 8;
                cp16(kbase + (r * KST + cc) * 2, Kp + r * 64 + cc);
            }
            #pragma unroll
            for (int i = 0; i < 4; i++) {
                int c = tid + i * 256;
                int r = c >> 4, cc = (c & 15) * 8;
                cp16(vbase + (r * VST + cc) * 2, Vg + (size_t)r * LL + (kt + 1) * 128 + cc);
            }
            cp_commit();
            cp_wait<1>();
        } else {
            cp_wait<0>();
        }
        __syncthreads();

        const unsigned Kb_ = smb + (QS_SZ + (kt & 1) * BUF_SZ) * 2;
        const unsigned Vb_ = Kb_ + KT_SZ * 2;

        // ---- S = Q @ K^T ----
        float s[16][4] = {};
        #pragma unroll
        for (int kk = 0; kk < 4; kk++) {
            #pragma unroll
            for (int nt2 = 0; nt2 < 8; nt2++) {
                unsigned r0, r1, r2, r3;
                unsigned addr = Kb_ +
                    (((nt2 * 16 + lrow + ln8) * KST) + kk * 16 + lh8) * 2;
                ldmx4(r0, r1, r2, r3, addr);
                mma16816(s[2 * nt2],     qa[kk], r0, r1);
                mma16816(s[2 * nt2 + 1], qa[kk], r2, r3);
            }
        }

        // ---- online softmax ----
        float mr0 = -1e30f, mr1 = -1e30f;
        #pragma unroll
        for (int nt = 0; nt < 16; nt++) {
            mr0 = fmaxf(mr0, fmaxf(s[nt][0], s[nt][1]));
            mr1 = fmaxf(mr1, fmaxf(s[nt][2], s[nt][3]));
        }
        mr0 = fmaxf(mr0, __shfl_xor_sync(0xffffffffu, mr0, 1));
        mr0 = fmaxf(mr0, __shfl_xor_sync(0xffffffffu, mr0, 2));
        mr1 = fmaxf(mr1, __shfl_xor_sync(0xffffffffu, mr1, 1));
        mr1 = fmaxf(mr1, __shfl_xor_sync(0xffffffffu, mr1, 2));
        float mn0 = fmaxf(m0, mr0), mn1 = fmaxf(m1, mr1);
        float al0 = ex2f(m0 - mn0), al1 = ex2f(m1 - mn1);
        m0 = mn0; m1 = mn1;

        unsigned aP[8][4];
        float lr0 = 0.f, lr1 = 0.f;
        #pragma unroll
        for (int nt = 0; nt < 16; nt++) {
            float p0 = ex2f(s[nt][0] - mn0);
            float p1 = ex2f(s[nt][1] - mn0);
            float p2 = ex2f(s[nt][2] - mn1);
            float p3 = ex2f(s[nt][3] - mn1);
            lr0 += p0 + p1; lr1 += p2 + p3;
            int k2 = nt >> 1, off = (nt & 1) * 2;
            aP[k2][off]     = packh2(p0, p1);
            aP[k2][off + 1] = packh2(p2, p3);
        }
        lr0 += __shfl_xor_sync(0xffffffffu, lr0, 1);
        lr0 += __shfl_xor_sync(0xffffffffu, lr0, 2);
        lr1 += __shfl_xor_sync(0xffffffffu, lr1, 1);
        lr1 += __shfl_xor_sync(0xffffffffu, lr1, 2);
        l0 = l0 * al0 + lr0;
        l1 = l1 * al1 + lr1;

        #pragma unroll
        for (int nt = 0; nt < 8; nt++) {
            o[nt][0] *= al0; o[nt][1] *= al0;
            o[nt][2] *= al1; o[nt][3] *= al1;
        }

        // ---- O += P @ V ----
        #pragma unroll
        for (int kt2 = 0; kt2 < 8; kt2++) {
            #pragma unroll
            for (int nt2 = 0; nt2 < 4; nt2++) {
                unsigned r0, r1, r2, r3;
                unsigned addr = Vb_ +
                    (((nt2 * 16 + lrow + ln8) * VST) + kt2 * 16 + lh8) * 2;
                ldmx4(r0, r1, r2, r3, addr);
                mma16816(o[2 * nt2],     aP[kt2], r0, r1);
                mma16816(o[2 * nt2 + 1], aP[kt2], r2, r3);
            }
        }
        __syncthreads();
    }

    // ---- epilogue ----
    float inv0 = 1.f / l0, inv1 = 1.f / l1;
    size_t row0 = (size_t)bI * 2048 + qt * 128 + w * 16 + g;
    #pragma unroll
    for (int nt = 0; nt < 8; nt++) {
        int col = h * 64 + nt * 8 + 2 * t;
        size_t o0 = row0 * DM + col;
        size_t o1 = (row0 + 8) * DM + col;
        *(__half2*)(g_O16 + o0) =
            __halves2half2(__float2half_rn(o[nt][0] * inv0),
                           __float2half_rn(o[nt][1] * inv0));
        *(__half2*)(g_O16 + o1) =
            __halves2half2(__float2half_rn(o[nt][2] * inv1),
                           __float2half_rn(o[nt][3] * inv1));
    }
}

// ---------------- row LayerNorm ----------------------------------------------
template <bool EMIT16>
__global__ __launch_bounds__(256) void ln_kernel(
    const float* __restrict__ y, const float* __restrict__ g,
    const float* __restrict__ bta, float* __restrict__ out,
    fp16* __restrict__ outh)
{
    __shared__ float s1[256], s2[256];
    const int row = blockIdx.x;
    const float* yr = y + (size_t)row * DM;
    float v[4];
    float a = 0.f, q = 0.f;
    #pragma unroll
    for (int i = 0; i < 4; i++) {
        v[i] = yr[threadIdx.x + i * 256];
        a += v[i]; q += v[i] * v[i];
    }
    s1[threadIdx.x] = a; s2[threadIdx.x] = q;
    __syncthreads();
    for (int st = 128; st > 0; st >>= 1) {
        if (threadIdx.x < st) {
            s1[threadIdx.x] += s1[threadIdx.x + st];
            s2[threadIdx.x] += s2[threadIdx.x + st];
        }
        __syncthreads();
    }
    const float mu = s1[0] * (1.f / DM);
    const float var = s2[0] * (1.f / DM) - mu * mu;
    const float rstd = rsqrtf(var + EPSLN);
    #pragma unroll
    for (int i = 0; i < 4; i++) {
        int c = threadIdx.x + i * 256;
        size_t o = (size_t)row * DM + c;
        float ov = (v[i] - mu) * rstd * g[c] + bta[c];
        out[o] = ov;
        if (EMIT16) outh[o] = __float2half_rn(ov);
    }
}

// ---------------- launch ------------------------------------------------------
extern "C" void kernel_launch(void* const* d_in, const int* in_sizes, int n_in,
                              void* d_out, int out_size)
{
    const float* x   = (const float*)d_in[0];
    const float* Wq  = (const float*)d_in[1];
    const float* bq  = (const float*)d_in[2];
    const float* Wk  = (const float*)d_in[3];
    const float* bk  = (const float*)d_in[4];
    const float* Wv  = (const float*)d_in[5];
    const float* bv  = (const float*)d_in[6];
    const float* Wo  = (const float*)d_in[7];
    const float* g1  = (const float*)d_in[8];
    const float* be1 = (const float*)d_in[9];
    const float* W1  = (const float*)d_in[10];
    const float* b1f = (const float*)d_in[11];
    const float* W2  = (const float*)d_in[12];
    const float* g2  = (const float*)d_in[13];
    const float* be2 = (const float*)d_in[14];
    float* out = (float*)d_out;

    void *px16, *pWq, *pWo, *pW1, *pW2, *pbq, *pO, *py1, *ph1, *ph116, *pff, *py2;
    cudaGetSymbolAddress(&px16, g_x16);
    cudaGetSymbolAddress(&pWq, g_Wqkv);
    cudaGetSymbolAddress(&pWo, g_Wo16);
    cudaGetSymbolAddress(&pW1, g_W116);
    cudaGetSymbolAddress(&pW2, g_W216);
    cudaGetSymbolAddress(&pbq, g_bqkv);
    cudaGetSymbolAddress(&pO, g_O16);
    cudaGetSymbolAddress(&py1, g_y1);
    cudaGetSymbolAddress(&ph1, g_h1);
    cudaGetSymbolAddress(&ph116, g_h116);
    cudaGetSymbolAddress(&pff, g_ff16);
    cudaGetSymbolAddress(&py2, g_y2);

    cudaFuncSetAttribute(gemm1_kernel<0>, cudaFuncAttributeMaxDynamicSharedMemorySize, GEMM_SMEM);
    cudaFuncSetAttribute(gemm1_kernel<1>, cudaFuncAttributeMaxDynamicSharedMemorySize, GEMM_SMEM);
    cudaFuncSetAttribute(gemm1_kernel<2>, cudaFuncAttributeMaxDynamicSharedMemorySize, GEMM_SMEM);
    cudaFuncSetAttribute(attn_kernel, cudaFuncAttributeMaxDynamicSharedMemorySize, ATTN_SMEM);

    // ---- prep
    xhalf_kernel<<<NROWS, 1024>>>(x);
    qkvw_kernel<<<dim3(2, 32, 48), dim3(32, 8)>>>(Wq, Wk, Wv);
    bqkv_kernel<<<3, 1024>>>(bq, bk, bv);
    thalf_kernel<<<dim3(32, 32),  dim3(32, 8)>>>(Wo, (fp16*)pWo, 1024, 1024);
    thalf_kernel<<<dim3(128, 32), dim3(32, 8)>>>(W1, (fp16*)pW1, 1024, 4096);
    thalf_kernel<<<dim3(32, 128), dim3(32, 8)>>>(W2, (fp16*)pW2, 4096, 1024);

    // ---- 1) QKV projection -> fp16 Q(scaled)/K/V^T
    gemm1_kernel<0><<<dim3(24, 32), 256, GEMM_SMEM>>>(
        (const fp16*)px16, (const fp16*)pWq, (const float*)pbq,
        nullptr, nullptr, nullptr, 1024, 3072);

    // ---- 2) tensor-core flash attention (fp16 operands)
    attn_kernel<<<dim3(16, HEADS), 256, ATTN_SMEM>>>();

    // ---- 3) O-proj + residual x -> y1
    gemm1_kernel<1><<<dim3(8, 32), 256, GEMM_SMEM>>>(
        (const fp16*)pO, (const fp16*)pWo, nullptr, x, (float*)py1, nullptr,
        1024, 1024);

    // ---- 4) LayerNorm 1 (fp32 + fp16 copy)
    ln_kernel<true><<<NROWS, 256>>>((const float*)py1, g1, be1,
                                    (float*)ph1, (fp16*)ph116);

    // ---- 5) FFN up + bias + ReLU -> fp16
    gemm1_kernel<2><<<dim3(32, 32), 256, GEMM_SMEM>>>(
        (const fp16*)ph116, (const fp16*)pW1, b1f, nullptr, nullptr, (fp16*)pff,
        1024, 4096);

    // ---- 6) FFN down + residual h1 -> y2
    gemm1_kernel<1><<<dim3(8, 32), 256, GEMM_SMEM>>>(
        (const fp16*)pff, (const fp16*)pW2, nullptr, (const float*)ph1,
        (float*)py2, nullptr, 4096, 1024);

    // ---- 7) LayerNorm 2 -> output
    ln_kernel<false><<<NROWS, 256>>>((const float*)py2, g2, be2, out, nullptr);
}

// round 7
// speedup vs baseline: 6.9178x; 1.0140x over previous
#include <cuda_runtime.h>
#include <cuda_fp16.h>

#define DM    1024
#define HH    16
#define DK    64
#define BB    2
#define LL    2048
#define NROWS (BB*LL)        /* 4096 */
#define DFF   4096
#define EPSLN 1e-5f
#define HEADS (BB*HH)

typedef __half fp16;

// scale for Q: 1/sqrt(64) * log2(e) so softmax can use exp2
#define QSCL 0.18033688011112042f

// ---------------- scratch (device globals; no allocations allowed) ----------
__device__ fp16  g_x16[(size_t)NROWS * DM];
__device__ fp16  g_Wqkv[3072ULL * 1024];      // [n=3072][k=1024]
__device__ fp16  g_Wo16[1024ULL * 1024];      // [n][k]
__device__ fp16  g_W116[4096ULL * 1024];      // [n=4096][k=1024]
__device__ fp16  g_W216[1024ULL * 4096];      // [n=1024][k=4096]
__device__ float g_bqkv[3072];
__device__ fp16  g_Qb[(size_t)HEADS * LL * DK];   // [bh][l][dk], pre-scaled
__device__ fp16  g_Kb[(size_t)HEADS * LL * DK];   // [bh][l][dk]
__device__ fp16  g_Vt[(size_t)HEADS * DK * LL];   // [bh][dk][l]  (transposed)
__device__ fp16  g_O16[(size_t)NROWS * DM];
__device__ float g_y1[(size_t)NROWS * DM];
__device__ float g_h1[(size_t)NROWS * DM];
__device__ fp16  g_h116[(size_t)NROWS * DM];
__device__ fp16  g_ff16[(size_t)NROWS * DFF];
__device__ float g_y2[(size_t)NROWS * DM];

__device__ __forceinline__ void mma16816(float* d, const unsigned* a,
                                         unsigned b0, unsigned b1) {
    asm volatile(
        "mma.sync.aligned.m16n8k16.row.col.f32.f16.f16.f32 "
        "{%0,%1,%2,%3}, {%4,%5,%6,%7}, {%8,%9}, {%0,%1,%2,%3};"
        : "+f"(d[0]), "+f"(d[1]), "+f"(d[2]), "+f"(d[3])
        : "r"(a[0]), "r"(a[1]), "r"(a[2]), "r"(a[3]), "r"(b0), "r"(b1));
}
__device__ __forceinline__ unsigned smem_u32(const void* p) {
    unsigned a;
    asm("{ .reg .u64 t; cvta.to.shared.u64 t, %1; cvt.u32.u64 %0, t; }"
        : "=r"(a) : "l"(p));
    return a;
}
__device__ __forceinline__ float ex2f(float x) {
    float y; asm("ex2.approx.f32 %0, %1;" : "=f"(y) : "f"(x)); return y;
}
__device__ __forceinline__ unsigned packh2(float lo, float hi) {
    unsigned r; asm("cvt.rn.f16x2.f32 %0, %1, %2;" : "=r"(r) : "f"(hi), "f"(lo));
    return r;
}
__device__ __forceinline__ void ldmx4(unsigned& r0, unsigned& r1, unsigned& r2,
                                      unsigned& r3, unsigned addr) {
    asm volatile("ldmatrix.sync.aligned.m8n8.x4.shared.b16 {%0,%1,%2,%3}, [%4];"
                 : "=r"(r0), "=r"(r1), "=r"(r2), "=r"(r3) : "r"(addr));
}
__device__ __forceinline__ void cp16(unsigned dst, const void* src) {
    asm volatile("cp.async.cg.shared.global [%0], [%1], 16;" :: "r"(dst), "l"(src));
}
__device__ __forceinline__ void cp_commit() {
    asm volatile("cp.async.commit_group;" ::: "memory");
}
template <int N>
__device__ __forceinline__ void cp_wait() {
    asm volatile("cp.async.wait_group %0;" :: "n"(N) : "memory");
}

// ---------------- fused prep kernel -------------------------------------------
// block ranges:
//  [0,2048)        x -> fp16
//  [2048,2060)     bqkv gather
//  [2060,5132)     QKV weights transpose+convert (3072)
//  [5132,6156)     Wo transpose (1024)
//  [6156,10252)    W1 transpose (4096)
//  [10252,14348)   W2 transpose (4096)
#define PREP_BLOCKS 14348

__device__ __forceinline__ void tblock(const float* __restrict__ src,
                                       fp16* __restrict__ d, float (*t)[33],
                                       int K, int N, int kb, int nb, int tid) {
    int tx = tid & 31, ty = tid >> 5;
    #pragma unroll
    for (int i = 0; i < 32; i += 8)
        t[ty + i][tx] = src[(size_t)(kb + ty + i) * N + nb + tx];
    __syncthreads();
    #pragma unroll
    for (int i = 0; i < 32; i += 8)
        d[(size_t)(nb + ty + i) * K + kb + tx] = __float2half_rn(t[tx][ty + i]);
}

__global__ __launch_bounds__(256) void prep_kernel(
    const float* __restrict__ x,
    const float* __restrict__ Wq, const float* __restrict__ Wk,
    const float* __restrict__ Wv,
    const float* __restrict__ bq, const float* __restrict__ bk,
    const float* __restrict__ bv,
    const float* __restrict__ Wo, const float* __restrict__ W1,
    const float* __restrict__ W2)
{
    __shared__ float t[32][33];
    const int blk = blockIdx.x, tid = threadIdx.x;

    if (blk < 2048) {
        size_t base = (size_t)blk * 2048 + tid * 8;
        float4 f0 = *(const float4*)(x + base);
        float4 f1 = *(const float4*)(x + base + 4);
        __half2 h[4];
        h[0] = __floats2half2_rn(f0.x, f0.y);
        h[1] = __floats2half2_rn(f0.z, f0.w);
        h[2] = __floats2half2_rn(f1.x, f1.y);
        h[3] = __floats2half2_rn(f1.z, f1.w);
        *(uint4*)(g_x16 + base) = *(uint4*)h;
    } else if (blk < 2060) {
        int i = (blk - 2048) * 256 + tid;
        int z = i >> 10, idx = i & 1023;
        const float* s = (z == 0) ? bq : (z == 1) ? bk : bv;
        g_bqkv[i] = s[idx];
    } else if (blk < 5132) {
        int p = blk - 2060;
        int bx = p & 1, by = (p >> 1) & 31, bz = p >> 6;
        int z = bz >> 4, h = bz & 15;
        const float* src = ((z == 0) ? Wq : (z == 1) ? Wk : Wv) + (size_t)h * DM * DK;
        int kb = by * 32, nb = bx * 32;
        int tx = tid & 31, ty = tid >> 5;
        #pragma unroll
        for (int i = 0; i < 32; i += 8)
            t[ty + i][tx] = src[(size_t)(kb + ty + i) * DK + nb + tx];
        __syncthreads();
        #pragma unroll
        for (int i = 0; i < 32; i += 8) {
            int ng = z * 1024 + h * 64 + nb + ty + i;
            g_Wqkv[(size_t)ng * DM + kb + tx] = __float2half_rn(t[tx][ty + i]);
        }
    } else if (blk < 6156) {
        int p = blk - 5132;
        tblock(Wo, g_Wo16, t, 1024, 1024, (p >> 5) * 32, (p & 31) * 32, tid);
    } else if (blk < 10252) {
        int p = blk - 6156;
        tblock(W1, g_W116, t, 1024, 4096, (p >> 7) * 32, (p & 127) * 32, tid);
    } else {
        int p = blk - 10252;
        tblock(W2, g_W216, t, 4096, 1024, (p >> 5) * 32, (p & 31) * 32, tid);
    }
}

// ---------------- fp16 mma.sync GEMM (3-stage cp.async, single sync) ---------
#define GST 72                        /* smem row stride (fp16) */
#define GTILE (128 * GST)             /* one 128x64 tile (padded) */
#define GSTAGE_B (2 * GTILE * 2)      /* bytes per stage: A + B tiles = 36864 */
#define GEMM_SMEM (3 * GSTAGE_B)      /* 110592 */

template <int EPI>
__global__ __launch_bounds__(256) void gemm1_kernel(
    const fp16* __restrict__ A, const fp16* __restrict__ B,
    const float* __restrict__ bias, const float* __restrict__ res,
    float* __restrict__ outf, fp16* __restrict__ outh,
    int K, int N)
{
    extern __shared__ fp16 smem[];
    const int tid = threadIdx.x;
    const int lane = tid & 31, wid = tid >> 5;
    const int wm = wid & 3, wn = wid >> 2;       // 4 x 2 warp grid
    const int g = lane >> 2, l2 = (lane & 3) * 2;
    const int m0 = blockIdx.y * 128, n0 = blockIdx.x * 128;
    const int nk = K >> 6;
    const unsigned smb = smem_u32(smem);

    // ldmatrix lane addressing
    const int lrow = lane & 7;
    const int arow = lrow + ((lane >> 3) & 1) * 8;
    const int acol = (lane >> 4) << 3;
    const int brow = lrow + ((lane >> 4) << 3);
    const int bcol = ((lane >> 3) & 1) << 3;

    // cp.async chunk addressing
    const int cr0 = tid >> 3;
    const int ccc = (tid & 7) * 8;

    float d[2][8][4] = {};

#define G_ISSUE(KS) do {                                                   \
        const int _k0 = (KS) << 6;                                         \
        unsigned _sb = smb + ((KS) % 3) * GSTAGE_B;                        \
        _Pragma("unroll")                                                  \
        for (int _i = 0; _i < 4; _i++) {                                   \
            int _r = cr0 + _i * 32;                                        \
            unsigned _off = (_r * GST + ccc) * 2;                          \
            cp16(_sb + _off,             A + (size_t)(m0 + _r) * K + _k0 + ccc); \
            cp16(_sb + GTILE * 2 + _off, B + (size_t)(n0 + _r) * K + _k0 + ccc); \
        }                                                                  \
        cp_commit();                                                       \
    } while (0)

    G_ISSUE(0);
    G_ISSUE(1);

    for (int ks = 0; ks < nk; ks++) {
        if (ks + 1 < nk) cp_wait<1>(); else cp_wait<0>();
        __syncthreads();
        if (ks + 2 < nk) G_ISSUE(ks + 2);

        const unsigned sA = smb + (ks % 3) * GSTAGE_B;
        const unsigned sB = sA + GTILE * 2;

        #pragma unroll
        for (int kk = 0; kk < 4; kk++) {
            unsigned a[2][4];
            #pragma unroll
            for (int mt = 0; mt < 2; mt++) {
                unsigned aoff = (((wm * 32 + mt * 16 + arow) * GST) + kk * 16 + acol) * 2;
                ldmx4(a[mt][0], a[mt][1], a[mt][2], a[mt][3], sA + aoff);
            }
            #pragma unroll
            for (int nt2 = 0; nt2 < 4; nt2++) {
                unsigned boff = (((wn * 64 + nt2 * 16 + brow) * GST) + kk * 16 + bcol) * 2;
                unsigned b0, b1, b2, b3;
                ldmx4(b0, b1, b2, b3, sB + boff);
                #pragma unroll
                for (int mt = 0; mt < 2; mt++) {
                    mma16816(d[mt][2 * nt2],     a[mt], b0, b1);
                    mma16816(d[mt][2 * nt2 + 1], a[mt], b2, b3);
                }
            }
        }
    }
#undef G_ISSUE

    // ---- epilogue ----
    #pragma unroll
    for (int mt = 0; mt < 2; mt++) {
        #pragma unroll
        for (int nt = 0; nt < 8; nt++) {
            int rbase = m0 + wm * 32 + mt * 16 + g;
            int cc = n0 + wn * 64 + nt * 8 + l2;
            #pragma unroll
            for (int rr = 0; rr < 2; rr++) {
                int rg = rbase + rr * 8;
                float v0 = d[mt][nt][rr * 2 + 0];
                float v1 = d[mt][nt][rr * 2 + 1];
                if (EPI == 0) {
                    float2 bv = *(const float2*)(bias + cc);
                    float w0 = v0 + bv.x, w1 = v1 + bv.y;
                    int z = cc >> 10, h = (cc >> 6) & 15, dk = cc & 63;
                    int bb_ = rg >> 11, lpos = rg & 2047;
                    size_t headbase = (size_t)(bb_ * 16 + h);
                    if (z == 0) {
                        w0 *= QSCL; w1 *= QSCL;
                        *(__half2*)(g_Qb + (headbase * 2048 + lpos) * 64 + dk) =
                            __halves2half2(__float2half_rn(w0), __float2half_rn(w1));
                    } else if (z == 1) {
                        *(__half2*)(g_Kb + (headbase * 2048 + lpos) * 64 + dk) =
                            __halves2half2(__float2half_rn(w0), __float2half_rn(w1));
                    } else {
                        size_t vb = (headbase * 64 + dk) * 2048 + lpos;
                        g_Vt[vb] = __float2half_rn(w0);
                        g_Vt[vb + 2048] = __float2half_rn(w1);
                    }
                } else if (EPI == 1) {
                    size_t o = (size_t)rg * N + cc;
                    float2 rv = *(const float2*)(res + o);
                    *(float2*)(outf + o) = make_float2(v0 + rv.x, v1 + rv.y);
                } else {
                    size_t o = (size_t)rg * N + cc;
                    float2 bv = *(const float2*)(bias + cc);
                    float w0 = fmaxf(v0 + bv.x, 0.f);
                    float w1 = fmaxf(v1 + bv.y, 0.f);
                    *(__half2*)(outh + o) =
                        __halves2half2(__float2half_rn(w0), __float2half_rn(w1));
                }
            }
        }
    }
}

// ---------------- fp16 flash attention (3-stage cp.async, single sync) -------
#define KST 72            /* K/Q smem row stride (fp16) */
#define VST 136           /* Vt smem row stride (fp16) */
#define QS_SZ   (128 * KST)
#define KT_SZ   (128 * KST)
#define VT_SZ   (64 * VST)
#define BUF_BYTES ((KT_SZ + VT_SZ) * 2)          /* 35840 */
#define ATTN_SMEM (QS_SZ * 2 + 3 * BUF_BYTES)    /* 125952 */

__global__ __launch_bounds__(256) void attn_kernel()
{
    extern __shared__ fp16 sm[];
    fp16* Qs = sm;
    const int tid = threadIdx.x, lane = tid & 31, w = tid >> 5;
    const int g = lane >> 2, t = lane & 3;
    const int qt = blockIdx.x, bh = blockIdx.y;
    const int bI = bh >> 4, h = bh & 15;

    const fp16* Qg = g_Qb + ((size_t)bh * LL + qt * 128) * 64;
    const fp16* Kg = g_Kb + (size_t)bh * LL * 64;
    const fp16* Vg = g_Vt + (size_t)bh * 64 * LL;
    const unsigned smb = smem_u32(sm);

#define A_ISSUE(KT) do {                                                       \
        unsigned _kbase = smb + QS_SZ * 2 + ((KT) % 3) * BUF_BYTES;            \
        unsigned _vbase = _kbase + KT_SZ * 2;                                  \
        const fp16* _Kp = Kg + (size_t)(KT) * 128 * 64;                        \
        _Pragma("unroll")                                                      \
        for (int _i = 0; _i < 4; _i++) {                                       \
            int _c = tid + _i * 256;                                           \
            int _r = _c >> 3, _cc = (_c & 7) * 8;                              \
            cp16(_kbase + (_r * KST + _cc) * 2, _Kp + _r * 64 + _cc);          \
        }                                                                      \
        _Pragma("unroll")                                                      \
        for (int _i = 0; _i < 4; _i++) {                                       \
            int _c = tid + _i * 256;                                           \
            int _r = _c >> 4, _cc = (_c & 15) * 8;                             \
            cp16(_vbase + (_r * VST + _cc) * 2,                                \
                 Vg + (size_t)_r * LL + (KT) * 128 + _cc);                     \
        }                                                                      \
        cp_commit();                                                           \
    } while (0)

    // stage Q (plain loads)
    #pragma unroll
    for (int i = 0; i < 4; i++) {
        int c = tid + i * 256;
        int r = c >> 3, cc = (c & 7) * 8;
        *(uint4*)(Qs + r * KST + cc) = *(const uint4*)(Qg + r * 64 + cc);
    }
    A_ISSUE(0);
    A_ISSUE(1);
    __syncthreads();

    // Q fragments (16x64 per warp)
    unsigned qa[4][4];
    {
        const int qrow = w * 16 + g;
        #pragma unroll
        for (int kk = 0; kk < 4; kk++) {
            qa[kk][0] = *(const unsigned*)(Qs + qrow * KST + kk * 16 + 2 * t);
            qa[kk][1] = *(const unsigned*)(Qs + (qrow + 8) * KST + kk * 16 + 2 * t);
            qa[kk][2] = *(const unsigned*)(Qs + qrow * KST + kk * 16 + 8 + 2 * t);
            qa[kk][3] = *(const unsigned*)(Qs + (qrow + 8) * KST + kk * 16 + 8 + 2 * t);
        }
    }

    float m0 = -1e30f, m1 = -1e30f, l0 = 0.f, l1 = 0.f;
    float o[8][4] = {};

    const int lrow = lane & 7;
    const int lh8  = ((lane >> 3) & 1) << 3;
    const int ln8  = (lane >> 4) << 3;

    for (int kt = 0; kt < 16; kt++) {
        if (kt + 1 < 16) cp_wait<1>(); else cp_wait<0>();
        __syncthreads();
        if (kt + 2 < 16) A_ISSUE(kt + 2);

        const unsigned Kb_ = smb + QS_SZ * 2 + (kt % 3) * BUF_BYTES;
        const unsigned Vb_ = Kb_ + KT_SZ * 2;

        // ---- S = Q @ K^T ----
        float s[16][4] = {};
        #pragma unroll
        for (int kk = 0; kk < 4; kk++) {
            #pragma unroll
            for (int nt2 = 0; nt2 < 8; nt2++) {
                unsigned r0, r1, r2, r3;
                unsigned addr = Kb_ +
                    (((nt2 * 16 + lrow + ln8) * KST) + kk * 16 + lh8) * 2;
                ldmx4(r0, r1, r2, r3, addr);
                mma16816(s[2 * nt2],     qa[kk], r0, r1);
                mma16816(s[2 * nt2 + 1], qa[kk], r2, r3);
            }
        }

        // ---- online softmax ----
        float mr0 = -1e30f, mr1 = -1e30f;
        #pragma unroll
        for (int nt = 0; nt < 16; nt++) {
            mr0 = fmaxf(mr0, fmaxf(s[nt][0], s[nt][1]));
            mr1 = fmaxf(mr1, fmaxf(s[nt][2], s[nt][3]));
        }
        mr0 = fmaxf(mr0, __shfl_xor_sync(0xffffffffu, mr0, 1));
        mr0 = fmaxf(mr0, __shfl_xor_sync(0xffffffffu, mr0, 2));
        mr1 = fmaxf(mr1, __shfl_xor_sync(0xffffffffu, mr1, 1));
        mr1 = fmaxf(mr1, __shfl_xor_sync(0xffffffffu, mr1, 2));
        float mn0 = fmaxf(m0, mr0), mn1 = fmaxf(m1, mr1);
        float al0 = ex2f(m0 - mn0), al1 = ex2f(m1 - mn1);
        m0 = mn0; m1 = mn1;

        unsigned aP[8][4];
        float lr0 = 0.f, lr1 = 0.f;
        #pragma unroll
        for (int nt = 0; nt < 16; nt++) {
            float p0 = ex2f(s[nt][0] - mn0);
            float p1 = ex2f(s[nt][1] - mn0);
            float p2 = ex2f(s[nt][2] - mn1);
            float p3 = ex2f(s[nt][3] - mn1);
            lr0 += p0 + p1; lr1 += p2 + p3;
            int k2 = nt >> 1, off = (nt & 1) * 2;
            aP[k2][off]     = packh2(p0, p1);
            aP[k2][off + 1] = packh2(p2, p3);
        }
        lr0 += __shfl_xor_sync(0xffffffffu, lr0, 1);
        lr0 += __shfl_xor_sync(0xffffffffu, lr0, 2);
        lr1 += __shfl_xor_sync(0xffffffffu, lr1, 1);
        lr1 += __shfl_xor_sync(0xffffffffu, lr1, 2);
        l0 = l0 * al0 + lr0;
        l1 = l1 * al1 + lr1;

        #pragma unroll
        for (int nt = 0; nt < 8; nt++) {
            o[nt][0] *= al0; o[nt][1] *= al0;
            o[nt][2] *= al1; o[nt][3] *= al1;
        }

        // ---- O += P @ V ----
        #pragma unroll
        for (int kt2 = 0; kt2 < 8; kt2++) {
            #pragma unroll
            for (int nt2 = 0; nt2 < 4; nt2++) {
                unsigned r0, r1, r2, r3;
                unsigned addr = Vb_ +
                    (((nt2 * 16 + lrow + ln8) * VST) + kt2 * 16 + lh8) * 2;
                ldmx4(r0, r1, r2, r3, addr);
                mma16816(o[2 * nt2],     aP[kt2], r0, r1);
                mma16816(o[2 * nt2 + 1], aP[kt2], r2, r3);
            }
        }
    }
#undef A_ISSUE

    // ---- epilogue ----
    float inv0 = 1.f / l0, inv1 = 1.f / l1;
    size_t row0 = (size_t)bI * 2048 + qt * 128 + w * 16 + g;
    #pragma unroll
    for (int nt = 0; nt < 8; nt++) {
        int col = h * 64 + nt * 8 + 2 * t;
        size_t o0 = row0 * DM + col;
        size_t o1 = (row0 + 8) * DM + col;
        *(__half2*)(g_O16 + o0) =
            __halves2half2(__float2half_rn(o[nt][0] * inv0),
                           __float2half_rn(o[nt][1] * inv0));
        *(__half2*)(g_O16 + o1) =
            __halves2half2(__float2half_rn(o[nt][2] * inv1),
                           __float2half_rn(o[nt][3] * inv1));
    }
}

// ---------------- row LayerNorm ----------------------------------------------
template <bool EMIT16>
__global__ __launch_bounds__(256) void ln_kernel(
    const float* __restrict__ y, const float* __restrict__ g,
    const float* __restrict__ bta, float* __restrict__ out,
    fp16* __restrict__ outh)
{
    __shared__ float s1[256], s2[256];
    const int row = blockIdx.x;
    const float* yr = y + (size_t)row * DM;
    float v[4];
    float a = 0.f, q = 0.f;
    #pragma unroll
    for (int i = 0; i < 4; i++) {
        v[i] = yr[threadIdx.x + i * 256];
        a += v[i]; q += v[i] * v[i];
    }
    s1[threadIdx.x] = a; s2[threadIdx.x] = q;
    __syncthreads();
    for (int st = 128; st > 0; st >>= 1) {
        if (threadIdx.x < st) {
            s1[threadIdx.x] += s1[threadIdx.x + st];
            s2[threadIdx.x] += s2[threadIdx.x + st];
        }
        __syncthreads();
    }
    const float mu = s1[0] * (1.f / DM);
    const float var = s2[0] * (1.f / DM) - mu * mu;
    const float rstd = rsqrtf(var + EPSLN);
    #pragma unroll
    for (int i = 0; i < 4; i++) {
        int c = threadIdx.x + i * 256;
        size_t o = (size_t)row * DM + c;
        float ov = (v[i] - mu) * rstd * g[c] + bta[c];
        out[o] = ov;
        if (EMIT16) outh[o] = __float2half_rn(ov);
    }
}

// ---------------- launch ------------------------------------------------------
extern "C" void kernel_launch(void* const* d_in, const int* in_sizes, int n_in,
                              void* d_out, int out_size)
{
    const float* x   = (const float*)d_in[0];
    const float* Wq  = (const float*)d_in[1];
    const float* bq  = (const float*)d_in[2];
    const float* Wk  = (const float*)d_in[3];
    const float* bk  = (const float*)d_in[4];
    const float* Wv  = (const float*)d_in[5];
    const float* bv  = (const float*)d_in[6];
    const float* Wo  = (const float*)d_in[7];
    const float* g1  = (const float*)d_in[8];
    const float* be1 = (const float*)d_in[9];
    const float* W1  = (const float*)d_in[10];
    const float* b1f = (const float*)d_in[11];
    const float* W2  = (const float*)d_in[12];
    const float* g2  = (const float*)d_in[13];
    const float* be2 = (const float*)d_in[14];
    float* out = (float*)d_out;

    void *px16, *pWq, *pWo, *pW1, *pW2, *pbq, *pO, *py1, *ph1, *ph116, *pff, *py2;
    cudaGetSymbolAddress(&px16, g_x16);
    cudaGetSymbolAddress(&pWq, g_Wqkv);
    cudaGetSymbolAddress(&pWo, g_Wo16);
    cudaGetSymbolAddress(&pW1, g_W116);
    cudaGetSymbolAddress(&pW2, g_W216);
    cudaGetSymbolAddress(&pbq, g_bqkv);
    cudaGetSymbolAddress(&pO, g_O16);
    cudaGetSymbolAddress(&py1, g_y1);
    cudaGetSymbolAddress(&ph1, g_h1);
    cudaGetSymbolAddress(&ph116, g_h116);
    cudaGetSymbolAddress(&pff, g_ff16);
    cudaGetSymbolAddress(&py2, g_y2);

    cudaFuncSetAttribute(gemm1_kernel<0>, cudaFuncAttributeMaxDynamicSharedMemorySize, GEMM_SMEM);
    cudaFuncSetAttribute(gemm1_kernel<1>, cudaFuncAttributeMaxDynamicSharedMemorySize, GEMM_SMEM);
    cudaFuncSetAttribute(gemm1_kernel<2>, cudaFuncAttributeMaxDynamicSharedMemorySize, GEMM_SMEM);
    cudaFuncSetAttribute(attn_kernel, cudaFuncAttributeMaxDynamicSharedMemorySize, ATTN_SMEM);

    // ---- prep (single fused launch)
    prep_kernel<<<PREP_BLOCKS, 256>>>(x, Wq, Wk, Wv, bq, bk, bv, Wo, W1, W2);

    // ---- 1) QKV projection -> fp16 Q(scaled)/K/V^T
    gemm1_kernel<0><<<dim3(24, 32), 256, GEMM_SMEM>>>(
        (const fp16*)px16, (const fp16*)pWq, (const float*)pbq,
        nullptr, nullptr, nullptr, 1024, 3072);

    // ---- 2) tensor-core flash attention (fp16 operands)
    attn_kernel<<<dim3(16, HEADS), 256, ATTN_SMEM>>>();

    // ---- 3) O-proj + residual x -> y1
    gemm1_kernel<1><<<dim3(8, 32), 256, GEMM_SMEM>>>(
        (const fp16*)pO, (const fp16*)pWo, nullptr, x, (float*)py1, nullptr,
        1024, 1024);

    // ---- 4) LayerNorm 1 (fp32 + fp16 copy)
    ln_kernel<true><<<NROWS, 256>>>((const float*)py1, g1, be1,
                                    (float*)ph1, (fp16*)ph116);

    // ---- 5) FFN up + bias + ReLU -> fp16
    gemm1_kernel<2><<<dim3(32, 32), 256, GEMM_SMEM>>>(
        (const fp16*)ph116, (const fp16*)pW1, b1f, nullptr, nullptr, (fp16*)pff,
        1024, 4096);

    // ---- 6) FFN down + residual h1 -> y2
    gemm1_kernel<1><<<dim3(8, 32), 256, GEMM_SMEM>>>(
        (const fp16*)pff, (const fp16*)pW2, nullptr, (const float*)ph1,
        (float*)py2, nullptr, 4096, 1024);

    // ---- 7) LayerNorm 2 -> output
    ln_kernel<false><<<NROWS, 256>>>((const float*)py2, g2, be2, out, nullptr);
}